// round 5
// baseline (speedup 1.0000x reference)
#include <cuda_runtime.h>
#include <cuda_bf16.h>
#include <cstdint>

// ---------------------------------------------------------------------------
// DQN_19198503813318 — R5: conv1 + conv2 on mma.sync (tf32 x3, hi/lo precomp).
// conv0/conv3/fc remain scalar.
// ---------------------------------------------------------------------------

#define BL 3072

__device__ float g_s0[BL * 32 * 21 * 21];   // after stage0 (planar)
__device__ float g_s1[BL * 32 * 9 * 9];     // after stage1
__device__ float g_s2[BL * 64 * 4 * 4];     // after stage2
__device__ float g_s3[BL * 256];            // flattened features
// conv1 weights, per (p, icq): [32 lanes][16 floats] (see k_w1prep)
__device__ float g_w1B[25 * 4 * 32 * 16];
// conv2 weights, per (p, icq): [32 lanes][32 floats] (see k_w2prep)
__device__ float g_w2B[16 * 4 * 32 * 32];

__device__ __forceinline__ float prelu(float v, float a) {
    return v >= 0.0f ? v : a * v;
}

__device__ __forceinline__ uint32_t tf32_hi(float v) {
    uint32_t h;
    asm("cvt.rna.tf32.f32 %0, %1;" : "=r"(h) : "f"(v));
    return h;
}

__device__ __forceinline__ void mma_tf32(float4& d,
                                         uint32_t a0, uint32_t a1, uint32_t a2, uint32_t a3,
                                         uint32_t b0, uint32_t b1) {
    asm volatile(
        "mma.sync.aligned.m16n8k8.row.col.f32.tf32.tf32.f32 "
        "{%0,%1,%2,%3}, {%4,%5,%6,%7}, {%8,%9}, {%0,%1,%2,%3};"
        : "+f"(d.x), "+f"(d.y), "+f"(d.z), "+f"(d.w)
        : "r"(a0), "r"(a1), "r"(a2), "r"(a3), "r"(b0), "r"(b1));
}

// ---------------------------------------------------------------------------
// conv1 weight prep: tf32 hi/lo split into per-fragment LDG.128 groups.
// grid = (25, 4) [p, icq], block = 512 (l = tid>>4, s = tid&15)
//   s: nf = s>>2, which = s&3 (0:hi k, 1:hi k+4, 2:lo k, 3:lo k+4)
//   n = nf*8 + (l>>2), k = icq*8 + (l&3) + (which&1)*4
// ---------------------------------------------------------------------------
__global__ void k_w1prep(const float* __restrict__ w1) {
    const int p   = blockIdx.x;
    const int icq = blockIdx.y;
    const int tid = threadIdx.x;
    const int l   = tid >> 4;
    const int s   = tid & 15;
    const int nf    = s >> 2;
    const int which = s & 3;
    const int n = nf * 8 + (l >> 2);
    const int k = icq * 8 + (l & 3) + (which & 1) * 4;
    float v = w1[n * 800 + k * 25 + p];
    float hi = __uint_as_float(tf32_hi(v));
    float outv;
    if (which < 2) outv = hi;
    else           outv = __uint_as_float(tf32_hi(v - hi));
    g_w1B[(((p * 4 + icq) * 32) + l) * 16 + s] = outv;
}

// ---------------------------------------------------------------------------
// conv2 weight prep. grid = (16, 4) [p, icq], block = 1024
//   lane = tid>>5, s = tid&31: half = s>>4 (0 hi / 1 lo), nf = (s>>1)&7, reg = s&1
//   n = nf*8 + (lane>>2), k = icq*8 + (lane&3) + reg*4
// ---------------------------------------------------------------------------
__global__ void k_w2prep(const float* __restrict__ w2) {
    const int p    = blockIdx.x;
    const int icq  = blockIdx.y;
    const int lane = threadIdx.x >> 5;
    const int s    = threadIdx.x & 31;
    const int half = s >> 4;
    const int nf   = (s >> 1) & 7;
    const int reg  = s & 1;
    const int n = nf * 8 + (lane >> 2);
    const int k = icq * 8 + (lane & 3) + reg * 4;
    float v = w2[n * 512 + k * 16 + p];
    float hi = __uint_as_float(tf32_hi(v));
    float outv = half ? __uint_as_float(tf32_hi(v - hi)) : hi;
    g_w2B[((p * 4 + icq) * 32 + lane) * 32 + s] = outv;
}

// ---------------------------------------------------------------------------
// Stage 1 (mma): conv(32->32,5x5,pad1)+prelu+pool2. grid=BL, block=224.
// smem: hiI[484][36], loI[484][36] (22x22 padded rows, channel-last, tf32 pre-
// rounded). MMA loop is pure LDS+MMA. Epilogue reuses hiI as stage buffer.
// ---------------------------------------------------------------------------
#define C1_STR  36
#define C1_IMGF (484 * 36)             // 17424 floats
#define SMEM_C1 (2 * C1_IMGF * 4)      // 139392 B

__global__ void __launch_bounds__(224, 1)
k_conv1_mma(const float* __restrict__ b, const float* __restrict__ ap) {
    extern __shared__ float sm1[];
    float* hiI = sm1;
    float* loI = sm1 + C1_IMGF;
    const int tid = threadIdx.x;
    const int wid = tid >> 5;
    const int lid = tid & 31;
    const int bl  = blockIdx.x;

    for (int i = tid; i < 2 * C1_IMGF; i += 224) sm1[i] = 0.0f;
    __syncthreads();
    const float* src = g_s0 + bl * 14112;
    for (int i = tid; i < 14112; i += 224) {
        int ic  = i / 441;
        int pix = i - ic * 441;
        int y   = pix / 21;
        int x   = pix - y * 21;
        int idx = ((y + 1) * 22 + (x + 1)) * C1_STR + ic;
        float v = src[i];
        float h = __uint_as_float(tf32_hi(v));
        hiI[idx] = h;
        loI[idx] = __uint_as_float(tf32_hi(v - h));
    }
    __syncthreads();

    int base[3][2];
#pragma unroll
    for (int t = 0; t < 3; ++t) {
#pragma unroll
        for (int j = 0; j < 2; ++j) {
            int m  = (wid * 3 + t) * 16 + (lid >> 2) + j * 8;
            int mm = m < 324 ? m : 0;
            int ym = mm / 18;
            int xm = mm - ym * 18;
            base[t][j] = (ym * 22 + xm) * C1_STR;
        }
    }

    float4 acc[3][4];
#pragma unroll
    for (int t = 0; t < 3; ++t)
#pragma unroll
        for (int nf = 0; nf < 4; ++nf)
            acc[t][nf] = make_float4(0.f, 0.f, 0.f, 0.f);

    const int cb = lid & 3;
    for (int p = 0; p < 25; ++p) {
        const int ky = p / 5;
        const int kx = p - ky * 5;
        const int off = (ky * 22 + kx) * C1_STR;
#pragma unroll
        for (int icq = 0; icq < 4; ++icq) {
            const float4* gB = (const float4*)(g_w1B + (((p * 4 + icq) * 32) + lid) * 16);
            float4 B0 = gB[0], B1 = gB[1], B2 = gB[2], B3 = gB[3];
            const int c = icq * 8 + cb;
#pragma unroll
            for (int t = 0; t < 3; ++t) {
                const int i00 = base[t][0] + off + c;
                const int i10 = base[t][1] + off + c;
                uint32_t h00 = __float_as_uint(hiI[i00]);
                uint32_t h10 = __float_as_uint(hiI[i10]);
                uint32_t h01 = __float_as_uint(hiI[i00 + 4]);
                uint32_t h11 = __float_as_uint(hiI[i10 + 4]);
                uint32_t l00 = __float_as_uint(loI[i00]);
                uint32_t l10 = __float_as_uint(loI[i10]);
                uint32_t l01 = __float_as_uint(loI[i00 + 4]);
                uint32_t l11 = __float_as_uint(loI[i10 + 4]);
                mma_tf32(acc[t][0], h00, h10, h01, h11,
                         __float_as_uint(B0.x), __float_as_uint(B0.y));
                mma_tf32(acc[t][1], h00, h10, h01, h11,
                         __float_as_uint(B1.x), __float_as_uint(B1.y));
                mma_tf32(acc[t][2], h00, h10, h01, h11,
                         __float_as_uint(B2.x), __float_as_uint(B2.y));
                mma_tf32(acc[t][3], h00, h10, h01, h11,
                         __float_as_uint(B3.x), __float_as_uint(B3.y));
                mma_tf32(acc[t][0], l00, l10, l01, l11,
                         __float_as_uint(B0.x), __float_as_uint(B0.y));
                mma_tf32(acc[t][1], l00, l10, l01, l11,
                         __float_as_uint(B1.x), __float_as_uint(B1.y));
                mma_tf32(acc[t][2], l00, l10, l01, l11,
                         __float_as_uint(B2.x), __float_as_uint(B2.y));
                mma_tf32(acc[t][3], l00, l10, l01, l11,
                         __float_as_uint(B3.x), __float_as_uint(B3.y));
                mma_tf32(acc[t][0], h00, h10, h01, h11,
                         __float_as_uint(B0.z), __float_as_uint(B0.w));
                mma_tf32(acc[t][1], h00, h10, h01, h11,
                         __float_as_uint(B1.z), __float_as_uint(B1.w));
                mma_tf32(acc[t][2], h00, h10, h01, h11,
                         __float_as_uint(B2.z), __float_as_uint(B2.w));
                mma_tf32(acc[t][3], h00, h10, h01, h11,
                         __float_as_uint(B3.z), __float_as_uint(B3.w));
            }
        }
    }
    __syncthreads();   // image no longer needed; reuse hiI as stage buffer

    const float a = *ap;
    float* stage = hiI;                 // 336 rows x stride 33 fits in 17424
    {
        const int r0 = (wid * 3) * 16 + (lid >> 2);
        const int oc0 = 2 * (lid & 3);
#pragma unroll
        for (int t = 0; t < 3; ++t) {
            int ra = r0 + t * 16;
            int rb = ra + 8;
#pragma unroll
            for (int nf = 0; nf < 4; ++nf) {
                int ca = nf * 8 + oc0;
                float ba = b[ca], bb = b[ca + 1];
                stage[ra * 33 + ca]     = prelu(acc[t][nf].x + ba, a);
                stage[ra * 33 + ca + 1] = prelu(acc[t][nf].y + bb, a);
                stage[rb * 33 + ca]     = prelu(acc[t][nf].z + ba, a);
                stage[rb * 33 + ca + 1] = prelu(acc[t][nf].w + bb, a);
            }
        }
    }
    __syncthreads();

    float* out = g_s1 + bl * 2592;
    for (int i = tid; i < 2592; i += 224) {
        int oc = i / 81;
        int pp = i - oc * 81;
        int py = pp / 9;
        int px = pp - py * 9;
        int m00 = (2 * py) * 18 + 2 * px;
        float v = fmaxf(fmaxf(stage[m00 * 33 + oc],        stage[(m00 + 1) * 33 + oc]),
                        fmaxf(stage[(m00 + 18) * 33 + oc], stage[(m00 + 19) * 33 + oc]));
        out[i] = v;
    }
}

// ---------------------------------------------------------------------------
// Stage 2 (mma): conv(32->64,4x4,pad1)+prelu+pool2. grid=BL/2, block=256.
// 2 images per CTA: M=128 (8 warps x 16 rows), N=64 (8 nf), K=16 pos x 32 ic.
// smem: hiI/loI [2 img][121 rows (11x11 padded)][36ch]; epilogue in hiI.
// ---------------------------------------------------------------------------
#define C2_STR  36
#define C2_IMGF (121 * 36)                  // 4356 per image
#define SMEM_C2 (2 * 2 * C2_IMGF * 4)       // 69696 B

__global__ void __launch_bounds__(256, 1)
k_conv2_mma(const float* __restrict__ b, const float* __restrict__ ap) {
    extern __shared__ float sm2[];
    float* hiI = sm2;                       // 2*4356 = 8712
    float* loI = sm2 + 2 * C2_IMGF;
    const int tid = threadIdx.x;
    const int wid = tid >> 5;
    const int lid = tid & 31;
    const int bl  = blockIdx.x;             // image pair

    for (int i = tid; i < 4 * C2_IMGF; i += 256) sm2[i] = 0.0f;
    __syncthreads();
    const float* src = g_s1 + bl * 2 * 2592;
    for (int i = tid; i < 2 * 2592; i += 256) {
        int img = i / 2592;
        int r   = i - img * 2592;
        int ic  = r / 81;
        int pix = r - ic * 81;
        int y   = pix / 9;
        int x   = pix - y * 9;
        int idx = img * C2_IMGF + ((y + 1) * 11 + (x + 1)) * C2_STR + ic;
        float v = src[i];
        float h = __uint_as_float(tf32_hi(v));
        hiI[idx] = h;
        loI[idx] = __uint_as_float(tf32_hi(v - h));
    }
    __syncthreads();

    // warp tile: rows m = wid*16 + (lid>>2) (+8); img = wid>>2
    const int img = wid >> 2;
    int base[2];
#pragma unroll
    for (int j = 0; j < 2; ++j) {
        int m   = wid * 16 + (lid >> 2) + j * 8;
        int pix = m & 63;
        int oy  = pix >> 3;
        int ox  = pix & 7;
        base[j] = img * C2_IMGF + (oy * 11 + ox) * C2_STR;
    }

    float4 acc[8];
#pragma unroll
    for (int nf = 0; nf < 8; ++nf) acc[nf] = make_float4(0.f, 0.f, 0.f, 0.f);

    const int cb = lid & 3;
    for (int p = 0; p < 16; ++p) {
        const int ky = p >> 2;
        const int kx = p & 3;
        const int off = (ky * 11 + kx) * C2_STR;
#pragma unroll
        for (int icq = 0; icq < 4; ++icq) {
            const float4* gB = (const float4*)(g_w2B + ((p * 4 + icq) * 32 + lid) * 32);
            float4 Bv[8];
#pragma unroll
            for (int j = 0; j < 8; ++j) Bv[j] = gB[j];
            const int c  = icq * 8 + cb;
            const int i0 = base[0] + off + c;
            const int i1 = base[1] + off + c;
            uint32_t h00 = __float_as_uint(hiI[i0]);
            uint32_t h10 = __float_as_uint(hiI[i1]);
            uint32_t h01 = __float_as_uint(hiI[i0 + 4]);
            uint32_t h11 = __float_as_uint(hiI[i1 + 4]);
            uint32_t l00 = __float_as_uint(loI[i0]);
            uint32_t l10 = __float_as_uint(loI[i1]);
            uint32_t l01 = __float_as_uint(loI[i0 + 4]);
            uint32_t l11 = __float_as_uint(loI[i1 + 4]);
#pragma unroll
            for (int nf = 0; nf < 8; ++nf) {
                float4 Bh = Bv[nf >> 1];
                float4 Bl = Bv[4 + (nf >> 1)];
                uint32_t bh0, bh1, bl0, bl1;
                if (nf & 1) {
                    bh0 = __float_as_uint(Bh.z); bh1 = __float_as_uint(Bh.w);
                    bl0 = __float_as_uint(Bl.z); bl1 = __float_as_uint(Bl.w);
                } else {
                    bh0 = __float_as_uint(Bh.x); bh1 = __float_as_uint(Bh.y);
                    bl0 = __float_as_uint(Bl.x); bl1 = __float_as_uint(Bl.y);
                }
                mma_tf32(acc[nf], h00, h10, h01, h11, bh0, bh1);
                mma_tf32(acc[nf], l00, l10, l01, l11, bh0, bh1);
                mma_tf32(acc[nf], h00, h10, h01, h11, bl0, bl1);
            }
        }
    }
    __syncthreads();   // reuse hiI as stage: 128 rows x stride 65 = 8320

    const float a = *ap;
    float* stage = hiI;
    {
        const int r0  = wid * 16 + (lid >> 2);
        const int oc0 = 2 * (lid & 3);
#pragma unroll
        for (int nf = 0; nf < 8; ++nf) {
            int ca = nf * 8 + oc0;
            float ba = b[ca], bb = b[ca + 1];
            stage[r0 * 65 + ca]           = prelu(acc[nf].x + ba, a);
            stage[r0 * 65 + ca + 1]       = prelu(acc[nf].y + bb, a);
            stage[(r0 + 8) * 65 + ca]     = prelu(acc[nf].z + ba, a);
            stage[(r0 + 8) * 65 + ca + 1] = prelu(acc[nf].w + bb, a);
        }
    }
    __syncthreads();

    // 2x2 maxpool -> planar g_s2 (BL,64,4,4)
    for (int i = tid; i < 2048; i += 256) {
        int im  = i >> 10;
        int rem = i & 1023;
        int oc  = rem >> 4;
        int pp  = rem & 15;
        int py  = pp >> 2;
        int px  = pp & 3;
        int m00 = im * 64 + (2 * py) * 8 + 2 * px;
        float v = fmaxf(fmaxf(stage[m00 * 65 + oc],       stage[(m00 + 1) * 65 + oc]),
                        fmaxf(stage[(m00 + 8) * 65 + oc], stage[(m00 + 9) * 65 + oc]));
        g_s2[((bl * 2 + im) * 64 + oc) * 16 + py * 4 + px] = v;
    }
}

// ---------------------------------------------------------------------------
// Stage 0 (scalar): conv(4->32,5x5,pad1)+prelu+pool2
// ---------------------------------------------------------------------------
__global__ void k_conv0(const float* __restrict__ x,
                        const float* __restrict__ w,
                        const float* __restrict__ b,
                        const float* __restrict__ ap) {
    extern __shared__ float smem[];
    float* sIn = smem;          // 4*46*46 = 8464
    float* sW  = smem + 8464;   // 32*101  = 3232
    const int bl  = blockIdx.x;
    const int tid = threadIdx.x;

    for (int i = tid; i < 8464; i += 224) sIn[i] = 0.0f;
    __syncthreads();
    const float* xb = x + bl * 8100;
    for (int i = tid; i < 8100; i += 224) {
        int ic = i / 2025;
        int r  = (i / 45) % 45;
        int c  = i % 45;
        sIn[ic * 2116 + (r + 1) * 46 + (c + 1)] = xb[i];
    }
    for (int k = tid; k < 3200; k += 224) {
        int oc = k / 100;
        sW[oc * 101 + (k % 100)] = w[k];
    }
    __syncthreads();

    const int oc = tid & 31;
    const int g  = tid >> 5;
    const float bias = b[oc];
    const float a = *ap;
    const float* wB = sW + oc * 101;

    for (int py = 0; py < 21; ++py) {
        float accA[6], accB[6];
#pragma unroll
        for (int j = 0; j < 6; ++j) { accA[j] = bias; accB[j] = bias; }
        const int y0 = 2 * py;
        for (int ic = 0; ic < 4; ++ic) {
            const float* inC = sIn + ic * 2116;
#pragma unroll
            for (int ky = 0; ky < 5; ++ky) {
                const float* r0 = inC + (y0 + ky) * 46 + 6 * g;
                const float* r1 = r0 + 46;
                float ra[10], rb[10];
#pragma unroll
                for (int j = 0; j < 10; ++j) { ra[j] = r0[j]; rb[j] = r1[j]; }
                const float* wv = wB + ic * 25 + ky * 5;
#pragma unroll
                for (int kx = 0; kx < 5; ++kx) {
                    float wk = wv[kx];
#pragma unroll
                    for (int j = 0; j < 6; ++j) {
                        accA[j] = fmaf(ra[j + kx], wk, accA[j]);
                        accB[j] = fmaf(rb[j + kx], wk, accB[j]);
                    }
                }
            }
        }
        float* o = g_s0 + ((bl * 32 + oc) * 21 + py) * 21 + 3 * g;
#pragma unroll
        for (int u = 0; u < 3; ++u) {
            float v0 = prelu(accA[2 * u], a);
            float v1 = prelu(accA[2 * u + 1], a);
            float v2 = prelu(accB[2 * u], a);
            float v3 = prelu(accB[2 * u + 1], a);
            o[u] = fmaxf(fmaxf(v0, v1), fmaxf(v2, v3));
        }
    }
}

// ---------------------------------------------------------------------------
// Stage 3 (scalar): conv(64->64,3x3,pad0)+prelu+flatten
// ---------------------------------------------------------------------------
__global__ void k_conv3(const float* __restrict__ w,
                        const float* __restrict__ b,
                        const float* __restrict__ ap) {
    extern __shared__ float smem[];
    float* sW  = smem;             // 64*577 = 36928
    float* sIn = smem + 36928;     // 8*1024 = 8192
    const int tid = threadIdx.x;
    const int bl0 = blockIdx.x * 8;

    for (int k = tid; k < 64 * 576; k += 256) {
        int oc = k / 576;
        sW[oc * 577 + (k % 576)] = w[k];
    }
    const float* src = g_s2 + bl0 * 1024;
    for (int i = tid; i < 8192; i += 256) sIn[i] = src[i];
    __syncthreads();

    const int oc  = tid >> 2;
    const int pos = tid & 3;
    const int yy  = pos >> 1;
    const int xx  = pos & 1;
    const float bias = b[oc];
    const float a = *ap;

    float acc[8];
#pragma unroll
    for (int i = 0; i < 8; ++i) acc[i] = bias;

    for (int ic = 0; ic < 64; ++ic) {
        const float* wv = sW + oc * 577 + ic * 9;
        float wr[9];
#pragma unroll
        for (int j = 0; j < 9; ++j) wr[j] = wv[j];
#pragma unroll
        for (int img = 0; img < 8; ++img) {
            const float* ip = sIn + img * 1024 + ic * 16;
#pragma unroll
            for (int ky = 0; ky < 3; ++ky)
#pragma unroll
                for (int kx = 0; kx < 3; ++kx)
                    acc[img] = fmaf(ip[(yy + ky) * 4 + (xx + kx)], wr[ky * 3 + kx], acc[img]);
        }
    }
#pragma unroll
    for (int img = 0; img < 8; ++img) {
        g_s3[(bl0 + img) * 256 + oc * 4 + pos] = prelu(acc[img], a);
    }
}

// ---------------------------------------------------------------------------
// FC heads
// ---------------------------------------------------------------------------
__global__ void k_fc(const float* __restrict__ fc1_w, const float* __restrict__ fc1_b,
                     const float* __restrict__ a4,
                     const float* __restrict__ fc2_w, const float* __restrict__ fc2_b,
                     const float* __restrict__ a5,
                     const float* __restrict__ fc3_w, const float* __restrict__ fc3_b,
                     float* __restrict__ out) {
    __shared__ float feat[256];
    __shared__ float h1[128];
    __shared__ float h2[64];
    const int bl  = blockIdx.x;
    const int l   = bl % 6;
    const int tid = threadIdx.x;

    feat[tid]       = g_s3[bl * 256 + tid];
    feat[tid + 128] = g_s3[bl * 256 + 128 + tid];
    __syncthreads();

    {
        float acc = fc1_b[l * 128 + tid];
        const float* W = fc1_w + l * 256 * 128 + tid;
#pragma unroll 8
        for (int i = 0; i < 256; ++i) acc = fmaf(feat[i], W[i * 128], acc);
        float av = a4[l];
        h1[tid] = prelu(acc, av);
    }
    __syncthreads();
    if (tid < 64) {
        float acc = fc2_b[l * 64 + tid];
        const float* W = fc2_w + l * 128 * 64 + tid;
#pragma unroll 8
        for (int i = 0; i < 128; ++i) acc = fmaf(h1[i], W[i * 64], acc);
        float av = a5[l];
        h2[tid] = prelu(acc, av);
    }
    __syncthreads();
    if (tid < 4) {
        float acc = fc3_b[l * 4 + tid];
        const float* W = fc3_w + l * 64 * 4 + tid;
#pragma unroll
        for (int i = 0; i < 64; ++i) acc = fmaf(h2[i], W[i * 4], acc);
        out[bl * 4 + tid] = acc;
    }
}

// ---------------------------------------------------------------------------
extern "C" void kernel_launch(void* const* d_in, const int* in_sizes, int n_in,
                              void* d_out, int out_size) {
    const float* x     = (const float*)d_in[0];
    const float* w0    = (const float*)d_in[1];
    const float* b0    = (const float*)d_in[2];
    const float* w1    = (const float*)d_in[3];
    const float* b1    = (const float*)d_in[4];
    const float* w2    = (const float*)d_in[5];
    const float* b2    = (const float*)d_in[6];
    const float* w3    = (const float*)d_in[7];
    const float* b3    = (const float*)d_in[8];
    const float* a0    = (const float*)d_in[9];
    const float* a1    = (const float*)d_in[10];
    const float* a2    = (const float*)d_in[11];
    const float* a3    = (const float*)d_in[12];
    const float* fc1_w = (const float*)d_in[13];
    const float* fc1_b = (const float*)d_in[14];
    const float* a4    = (const float*)d_in[15];
    const float* fc2_w = (const float*)d_in[16];
    const float* fc2_b = (const float*)d_in[17];
    const float* a5    = (const float*)d_in[18];
    const float* fc3_w = (const float*)d_in[19];
    const float* fc3_b = (const float*)d_in[20];
    float* out = (float*)d_out;

    const int smem0 = (8464 + 3232) * 4;
    const int smem3 = (36928 + 8192) * 4;

    cudaFuncSetAttribute(k_conv0, cudaFuncAttributeMaxDynamicSharedMemorySize, smem0);
    cudaFuncSetAttribute(k_conv1_mma, cudaFuncAttributeMaxDynamicSharedMemorySize, SMEM_C1);
    cudaFuncSetAttribute(k_conv2_mma, cudaFuncAttributeMaxDynamicSharedMemorySize, SMEM_C2);
    cudaFuncSetAttribute(k_conv3, cudaFuncAttributeMaxDynamicSharedMemorySize, smem3);

    k_w1prep<<<dim3(25, 4), 512>>>(w1);
    k_w2prep<<<dim3(16, 4), 1024>>>(w2);
    k_conv0<<<BL, 224, smem0>>>(x, w0, b0, a0);
    k_conv1_mma<<<BL, 224, SMEM_C1>>>(b1, a1);
    k_conv2_mma<<<BL / 2, 256, SMEM_C2>>>(b2, a2);
    k_conv3<<<BL / 8, 256, smem3>>>(w3, b3, a3);
    k_fc<<<BL, 128>>>(fc1_w, fc1_b, a4, fc2_w, fc2_b, a5, fc3_w, fc3_b, out);
}

// round 6
// speedup vs baseline: 1.2268x; 1.2268x over previous
#include <cuda_runtime.h>
#include <cuda_bf16.h>
#include <cstdint>

// ---------------------------------------------------------------------------
// DQN_19198503813318 — R6: conv1+conv2 mma.sync tf32 x3; inline hi/lo cvt,
// conflict-free stride-36 SMEM, 2 CTAs/SM. conv0/conv3/fc scalar.
// ---------------------------------------------------------------------------

#define BL 3072

__device__ float g_s0[BL * 32 * 21 * 21];   // after stage0 (planar)
__device__ float g_s1[BL * 32 * 9 * 9];     // after stage1
__device__ float g_s2[BL * 64 * 4 * 4];     // after stage2
__device__ float g_s3[BL * 256];            // flattened features
__device__ float g_w1B[25 * 4 * 32 * 16];   // conv1 W frags (see k_w1prep)
__device__ float g_w2B[16 * 4 * 32 * 32];   // conv2 W frags (see k_w2prep)

__device__ __forceinline__ float prelu(float v, float a) {
    return v >= 0.0f ? v : a * v;
}

__device__ __forceinline__ uint32_t tf32_hi(float v) {
    uint32_t h;
    asm("cvt.rna.tf32.f32 %0, %1;" : "=r"(h) : "f"(v));
    return h;
}

__device__ __forceinline__ void mma_tf32(float4& d,
                                         uint32_t a0, uint32_t a1, uint32_t a2, uint32_t a3,
                                         uint32_t b0, uint32_t b1) {
    asm volatile(
        "mma.sync.aligned.m16n8k8.row.col.f32.tf32.tf32.f32 "
        "{%0,%1,%2,%3}, {%4,%5,%6,%7}, {%8,%9}, {%0,%1,%2,%3};"
        : "+f"(d.x), "+f"(d.y), "+f"(d.z), "+f"(d.w)
        : "r"(a0), "r"(a1), "r"(a2), "r"(a3), "r"(b0), "r"(b1));
}

// ---------------------------------------------------------------------------
// conv1 weight prep: grid=(25,4)[p,icq], block=512 (l=tid>>4, s=tid&15)
//   s: nf=s>>2, which=s&3 (0:hi k, 1:hi k+4, 2:lo k, 3:lo k+4)
//   n = nf*8 + (l>>2), k = icq*8 + (l&3) + (which&1)*4
// ---------------------------------------------------------------------------
__global__ void k_w1prep(const float* __restrict__ w1) {
    const int p   = blockIdx.x;
    const int icq = blockIdx.y;
    const int tid = threadIdx.x;
    const int l   = tid >> 4;
    const int s   = tid & 15;
    const int nf    = s >> 2;
    const int which = s & 3;
    const int n = nf * 8 + (l >> 2);
    const int k = icq * 8 + (l & 3) + (which & 1) * 4;
    float v = w1[n * 800 + k * 25 + p];
    float hi = __uint_as_float(tf32_hi(v));
    float outv;
    if (which < 2) outv = hi;
    else           outv = __uint_as_float(tf32_hi(v - hi));
    g_w1B[(((p * 4 + icq) * 32) + l) * 16 + s] = outv;
}

// ---------------------------------------------------------------------------
// conv2 weight prep: grid=(16,4)[p,icq], block=1024
//   lane=tid>>5, s=tid&31: half=s>>4 (0 hi/1 lo), nf=(s>>1)&7, reg=s&1
//   n = nf*8 + (lane>>2), k = icq*8 + (lane&3) + reg*4
// ---------------------------------------------------------------------------
__global__ void k_w2prep(const float* __restrict__ w2) {
    const int p    = blockIdx.x;
    const int icq  = blockIdx.y;
    const int lane = threadIdx.x >> 5;
    const int s    = threadIdx.x & 31;
    const int half = s >> 4;
    const int nf   = (s >> 1) & 7;
    const int reg  = s & 1;
    const int n = nf * 8 + (lane >> 2);
    const int k = icq * 8 + (lane & 3) + reg * 4;
    float v = w2[n * 512 + k * 16 + p];
    float hi = __uint_as_float(tf32_hi(v));
    float outv = half ? __uint_as_float(tf32_hi(v - hi)) : hi;
    g_w2B[((p * 4 + icq) * 32 + lane) * 32 + s] = outv;
}

// ---------------------------------------------------------------------------
// Stage 1 (mma): conv(32->32,5x5,pad1)+prelu+pool2. grid=BL, block=224.
// imgCL: 22x22 padded rows x stride 36 (bank = 4*row+c -> conflict-free).
// ---------------------------------------------------------------------------
#define C1_STR  36
#define C1_IMGF (484 * C1_STR)          // 17424 floats
#define SMEM_C1 (C1_IMGF * 4)           // 69696 B

__global__ void __launch_bounds__(224, 2)
k_conv1_mma(const float* __restrict__ b, const float* __restrict__ ap) {
    extern __shared__ float imgCL[];
    const int tid = threadIdx.x;
    const int wid = tid >> 5;
    const int lid = tid & 31;
    const int bl  = blockIdx.x;

    for (int i = tid; i < C1_IMGF; i += 224) imgCL[i] = 0.0f;
    __syncthreads();
    const float* src = g_s0 + bl * 14112;
    for (int i = tid; i < 14112; i += 224) {
        int ic  = i / 441;
        int pix = i - ic * 441;
        int y   = pix / 21;
        int x   = pix - y * 21;
        imgCL[((y + 1) * 22 + (x + 1)) * C1_STR + ic] = src[i];
    }
    __syncthreads();

    int base[3][2];
#pragma unroll
    for (int t = 0; t < 3; ++t) {
#pragma unroll
        for (int j = 0; j < 2; ++j) {
            int m  = (wid * 3 + t) * 16 + (lid >> 2) + j * 8;
            int mm = m < 324 ? m : 0;
            int ym = mm / 18;
            int xm = mm - ym * 18;
            base[t][j] = (ym * 22 + xm) * C1_STR;
        }
    }

    float4 acc[3][4];
#pragma unroll
    for (int t = 0; t < 3; ++t)
#pragma unroll
        for (int nf = 0; nf < 4; ++nf)
            acc[t][nf] = make_float4(0.f, 0.f, 0.f, 0.f);

    const int cb = lid & 3;
    for (int p = 0; p < 25; ++p) {
        const int ky = p / 5;
        const int kx = p - ky * 5;
        const int off = (ky * 22 + kx) * C1_STR;
#pragma unroll
        for (int icq = 0; icq < 4; ++icq) {
            const float4* gB = (const float4*)(g_w1B + (((p * 4 + icq) * 32) + lid) * 16);
            float4 B0 = gB[0], B1 = gB[1], B2 = gB[2], B3 = gB[3];
            const int c = icq * 8 + cb;
#pragma unroll
            for (int t = 0; t < 3; ++t) {
                float v00 = imgCL[base[t][0] + off + c];
                float v10 = imgCL[base[t][1] + off + c];
                float v01 = imgCL[base[t][0] + off + c + 4];
                float v11 = imgCL[base[t][1] + off + c + 4];
                uint32_t h00 = tf32_hi(v00), h10 = tf32_hi(v10);
                uint32_t h01 = tf32_hi(v01), h11 = tf32_hi(v11);
                uint32_t l00 = tf32_hi(v00 - __uint_as_float(h00));
                uint32_t l10 = tf32_hi(v10 - __uint_as_float(h10));
                uint32_t l01 = tf32_hi(v01 - __uint_as_float(h01));
                uint32_t l11 = tf32_hi(v11 - __uint_as_float(h11));
                mma_tf32(acc[t][0], h00, h10, h01, h11,
                         __float_as_uint(B0.x), __float_as_uint(B0.y));
                mma_tf32(acc[t][1], h00, h10, h01, h11,
                         __float_as_uint(B1.x), __float_as_uint(B1.y));
                mma_tf32(acc[t][2], h00, h10, h01, h11,
                         __float_as_uint(B2.x), __float_as_uint(B2.y));
                mma_tf32(acc[t][3], h00, h10, h01, h11,
                         __float_as_uint(B3.x), __float_as_uint(B3.y));
                mma_tf32(acc[t][0], l00, l10, l01, l11,
                         __float_as_uint(B0.x), __float_as_uint(B0.y));
                mma_tf32(acc[t][1], l00, l10, l01, l11,
                         __float_as_uint(B1.x), __float_as_uint(B1.y));
                mma_tf32(acc[t][2], l00, l10, l01, l11,
                         __float_as_uint(B2.x), __float_as_uint(B2.y));
                mma_tf32(acc[t][3], l00, l10, l01, l11,
                         __float_as_uint(B3.x), __float_as_uint(B3.y));
                mma_tf32(acc[t][0], h00, h10, h01, h11,
                         __float_as_uint(B0.z), __float_as_uint(B0.w));
                mma_tf32(acc[t][1], h00, h10, h01, h11,
                         __float_as_uint(B1.z), __float_as_uint(B1.w));
                mma_tf32(acc[t][2], h00, h10, h01, h11,
                         __float_as_uint(B2.z), __float_as_uint(B2.w));
                mma_tf32(acc[t][3], h00, h10, h01, h11,
                         __float_as_uint(B3.z), __float_as_uint(B3.w));
            }
        }
    }
    __syncthreads();   // reuse imgCL as stage buffer (336 rows x stride 33)

    const float a = *ap;
    float* stage = imgCL;
    {
        const int r0 = (wid * 3) * 16 + (lid >> 2);
        const int oc0 = 2 * (lid & 3);
#pragma unroll
        for (int t = 0; t < 3; ++t) {
            int ra = r0 + t * 16;
            int rb = ra + 8;
#pragma unroll
            for (int nf = 0; nf < 4; ++nf) {
                int ca = nf * 8 + oc0;
                float ba = b[ca], bb = b[ca + 1];
                stage[ra * 33 + ca]     = prelu(acc[t][nf].x + ba, a);
                stage[ra * 33 + ca + 1] = prelu(acc[t][nf].y + bb, a);
                stage[rb * 33 + ca]     = prelu(acc[t][nf].z + ba, a);
                stage[rb * 33 + ca + 1] = prelu(acc[t][nf].w + bb, a);
            }
        }
    }
    __syncthreads();

    float* out = g_s1 + bl * 2592;
    for (int i = tid; i < 2592; i += 224) {
        int oc = i / 81;
        int pp = i - oc * 81;
        int py = pp / 9;
        int px = pp - py * 9;
        int m00 = (2 * py) * 18 + 2 * px;
        float v = fmaxf(fmaxf(stage[m00 * 33 + oc],        stage[(m00 + 1) * 33 + oc]),
                        fmaxf(stage[(m00 + 18) * 33 + oc], stage[(m00 + 19) * 33 + oc]));
        out[i] = v;
    }
}

// ---------------------------------------------------------------------------
// Stage 2 (mma): conv(32->64,4x4,pad1)+prelu+pool2. grid=BL/2, block=256.
// 2 images/CTA: M=128 (8 warps x 16 rows), N=64 (8 nf), K=16 pos x 32 ic.
// imgCL: [2 img][121 rows (11x11 padded)][stride 36]; inline hi/lo cvt.
// ---------------------------------------------------------------------------
#define C2_STR  36
#define C2_IMGF (121 * C2_STR)              // 4356 per image
#define SMEM_C2 (2 * C2_IMGF * 4)           // 34848 B

__global__ void __launch_bounds__(256, 2)
k_conv2_mma(const float* __restrict__ b, const float* __restrict__ ap) {
    extern __shared__ float imgC2[];
    const int tid = threadIdx.x;
    const int wid = tid >> 5;
    const int lid = tid & 31;
    const int bl  = blockIdx.x;             // image pair

    for (int i = tid; i < 2 * C2_IMGF; i += 256) imgC2[i] = 0.0f;
    __syncthreads();
    const float* src = g_s1 + bl * 2 * 2592;
    for (int i = tid; i < 2 * 2592; i += 256) {
        int img = i / 2592;
        int r   = i - img * 2592;
        int ic  = r / 81;
        int pix = r - ic * 81;
        int y   = pix / 9;
        int x   = pix - y * 9;
        imgC2[img * C2_IMGF + ((y + 1) * 11 + (x + 1)) * C2_STR + ic] = src[i];
    }
    __syncthreads();

    const int img = wid >> 2;
    int base[2];
#pragma unroll
    for (int j = 0; j < 2; ++j) {
        int m   = wid * 16 + (lid >> 2) + j * 8;
        int pix = m & 63;
        int oy  = pix >> 3;
        int ox  = pix & 7;
        base[j] = img * C2_IMGF + (oy * 11 + ox) * C2_STR;
    }

    float4 acc[8];
#pragma unroll
    for (int nf = 0; nf < 8; ++nf) acc[nf] = make_float4(0.f, 0.f, 0.f, 0.f);

    const int cb = lid & 3;
    for (int p = 0; p < 16; ++p) {
        const int ky = p >> 2;
        const int kx = p & 3;
        const int off = (ky * 11 + kx) * C2_STR;
#pragma unroll
        for (int icq = 0; icq < 4; ++icq) {
            const float4* gB = (const float4*)(g_w2B + ((p * 4 + icq) * 32 + lid) * 32);
            float4 Bv[8];
#pragma unroll
            for (int j = 0; j < 8; ++j) Bv[j] = gB[j];
            const int c  = icq * 8 + cb;
            const int i0 = base[0] + off + c;
            const int i1 = base[1] + off + c;
            float v00 = imgC2[i0];
            float v10 = imgC2[i1];
            float v01 = imgC2[i0 + 4];
            float v11 = imgC2[i1 + 4];
            uint32_t h00 = tf32_hi(v00), h10 = tf32_hi(v10);
            uint32_t h01 = tf32_hi(v01), h11 = tf32_hi(v11);
            uint32_t l00 = tf32_hi(v00 - __uint_as_float(h00));
            uint32_t l10 = tf32_hi(v10 - __uint_as_float(h10));
            uint32_t l01 = tf32_hi(v01 - __uint_as_float(h01));
            uint32_t l11 = tf32_hi(v11 - __uint_as_float(h11));
#pragma unroll
            for (int nf = 0; nf < 8; ++nf) {
                float4 Bh = Bv[nf >> 1];
                float4 Bl = Bv[4 + (nf >> 1)];
                uint32_t bh0, bh1, bl0, bl1;
                if (nf & 1) {
                    bh0 = __float_as_uint(Bh.z); bh1 = __float_as_uint(Bh.w);
                    bl0 = __float_as_uint(Bl.z); bl1 = __float_as_uint(Bl.w);
                } else {
                    bh0 = __float_as_uint(Bh.x); bh1 = __float_as_uint(Bh.y);
                    bl0 = __float_as_uint(Bl.x); bl1 = __float_as_uint(Bl.y);
                }
                mma_tf32(acc[nf], h00, h10, h01, h11, bh0, bh1);
                mma_tf32(acc[nf], l00, l10, l01, l11, bh0, bh1);
                mma_tf32(acc[nf], h00, h10, h01, h11, bl0, bl1);
            }
        }
    }
    __syncthreads();   // reuse imgC2 as stage: 128 rows x stride 65 = 8320

    const float a = *ap;
    float* stage = imgC2;
    {
        const int r0  = wid * 16 + (lid >> 2);
        const int oc0 = 2 * (lid & 3);
#pragma unroll
        for (int nf = 0; nf < 8; ++nf) {
            int ca = nf * 8 + oc0;
            float ba = b[ca], bb = b[ca + 1];
            stage[r0 * 65 + ca]           = prelu(acc[nf].x + ba, a);
            stage[r0 * 65 + ca + 1]       = prelu(acc[nf].y + bb, a);
            stage[(r0 + 8) * 65 + ca]     = prelu(acc[nf].z + ba, a);
            stage[(r0 + 8) * 65 + ca + 1] = prelu(acc[nf].w + bb, a);
        }
    }
    __syncthreads();

    for (int i = tid; i < 2048; i += 256) {
        int im  = i >> 10;
        int rem = i & 1023;
        int oc  = rem >> 4;
        int pp  = rem & 15;
        int py  = pp >> 2;
        int px  = pp & 3;
        int m00 = im * 64 + (2 * py) * 8 + 2 * px;
        float v = fmaxf(fmaxf(stage[m00 * 65 + oc],       stage[(m00 + 1) * 65 + oc]),
                        fmaxf(stage[(m00 + 8) * 65 + oc], stage[(m00 + 9) * 65 + oc]));
        g_s2[((bl * 2 + im) * 64 + oc) * 16 + py * 4 + px] = v;
    }
}

// ---------------------------------------------------------------------------
// Stage 0 (scalar): conv(4->32,5x5,pad1)+prelu+pool2
// ---------------------------------------------------------------------------
__global__ void k_conv0(const float* __restrict__ x,
                        const float* __restrict__ w,
                        const float* __restrict__ b,
                        const float* __restrict__ ap) {
    extern __shared__ float smem[];
    float* sIn = smem;          // 4*46*46 = 8464
    float* sW  = smem + 8464;   // 32*101  = 3232
    const int bl  = blockIdx.x;
    const int tid = threadIdx.x;

    for (int i = tid; i < 8464; i += 224) sIn[i] = 0.0f;
    __syncthreads();
    const float* xb = x + bl * 8100;
    for (int i = tid; i < 8100; i += 224) {
        int ic = i / 2025;
        int r  = (i / 45) % 45;
        int c  = i % 45;
        sIn[ic * 2116 + (r + 1) * 46 + (c + 1)] = xb[i];
    }
    for (int k = tid; k < 3200; k += 224) {
        int oc = k / 100;
        sW[oc * 101 + (k % 100)] = w[k];
    }
    __syncthreads();

    const int oc = tid & 31;
    const int g  = tid >> 5;
    const float bias = b[oc];
    const float a = *ap;
    const float* wB = sW + oc * 101;

    for (int py = 0; py < 21; ++py) {
        float accA[6], accB[6];
#pragma unroll
        for (int j = 0; j < 6; ++j) { accA[j] = bias; accB[j] = bias; }
        const int y0 = 2 * py;
        for (int ic = 0; ic < 4; ++ic) {
            const float* inC = sIn + ic * 2116;
#pragma unroll
            for (int ky = 0; ky < 5; ++ky) {
                const float* r0 = inC + (y0 + ky) * 46 + 6 * g;
                const float* r1 = r0 + 46;
                float ra[10], rb[10];
#pragma unroll
                for (int j = 0; j < 10; ++j) { ra[j] = r0[j]; rb[j] = r1[j]; }
                const float* wv = wB + ic * 25 + ky * 5;
#pragma unroll
                for (int kx = 0; kx < 5; ++kx) {
                    float wk = wv[kx];
#pragma unroll
                    for (int j = 0; j < 6; ++j) {
                        accA[j] = fmaf(ra[j + kx], wk, accA[j]);
                        accB[j] = fmaf(rb[j + kx], wk, accB[j]);
                    }
                }
            }
        }
        float* o = g_s0 + ((bl * 32 + oc) * 21 + py) * 21 + 3 * g;
#pragma unroll
        for (int u = 0; u < 3; ++u) {
            float v0 = prelu(accA[2 * u], a);
            float v1 = prelu(accA[2 * u + 1], a);
            float v2 = prelu(accB[2 * u], a);
            float v3 = prelu(accB[2 * u + 1], a);
            o[u] = fmaxf(fmaxf(v0, v1), fmaxf(v2, v3));
        }
    }
}

// ---------------------------------------------------------------------------
// Stage 3 (scalar): conv(64->64,3x3,pad0)+prelu+flatten
// ---------------------------------------------------------------------------
__global__ void k_conv3(const float* __restrict__ w,
                        const float* __restrict__ b,
                        const float* __restrict__ ap) {
    extern __shared__ float smem[];
    float* sW  = smem;             // 64*577 = 36928
    float* sIn = smem + 36928;     // 8*1024 = 8192
    const int tid = threadIdx.x;
    const int bl0 = blockIdx.x * 8;

    for (int k = tid; k < 64 * 576; k += 256) {
        int oc = k / 576;
        sW[oc * 577 + (k % 576)] = w[k];
    }
    const float* src = g_s2 + bl0 * 1024;
    for (int i = tid; i < 8192; i += 256) sIn[i] = src[i];
    __syncthreads();

    const int oc  = tid >> 2;
    const int pos = tid & 3;
    const int yy  = pos >> 1;
    const int xx  = pos & 1;
    const float bias = b[oc];
    const float a = *ap;

    float acc[8];
#pragma unroll
    for (int i = 0; i < 8; ++i) acc[i] = bias;

    for (int ic = 0; ic < 64; ++ic) {
        const float* wv = sW + oc * 577 + ic * 9;
        float wr[9];
#pragma unroll
        for (int j = 0; j < 9; ++j) wr[j] = wv[j];
#pragma unroll
        for (int img = 0; img < 8; ++img) {
            const float* ip = sIn + img * 1024 + ic * 16;
#pragma unroll
            for (int ky = 0; ky < 3; ++ky)
#pragma unroll
                for (int kx = 0; kx < 3; ++kx)
                    acc[img] = fmaf(ip[(yy + ky) * 4 + (xx + kx)], wr[ky * 3 + kx], acc[img]);
        }
    }
#pragma unroll
    for (int img = 0; img < 8; ++img) {
        g_s3[(bl0 + img) * 256 + oc * 4 + pos] = prelu(acc[img], a);
    }
}

// ---------------------------------------------------------------------------
// FC heads
// ---------------------------------------------------------------------------
__global__ void k_fc(const float* __restrict__ fc1_w, const float* __restrict__ fc1_b,
                     const float* __restrict__ a4,
                     const float* __restrict__ fc2_w, const float* __restrict__ fc2_b,
                     const float* __restrict__ a5,
                     const float* __restrict__ fc3_w, const float* __restrict__ fc3_b,
                     float* __restrict__ out) {
    __shared__ float feat[256];
    __shared__ float h1[128];
    __shared__ float h2[64];
    const int bl  = blockIdx.x;
    const int l   = bl % 6;
    const int tid = threadIdx.x;

    feat[tid]       = g_s3[bl * 256 + tid];
    feat[tid + 128] = g_s3[bl * 256 + 128 + tid];
    __syncthreads();

    {
        float acc = fc1_b[l * 128 + tid];
        const float* W = fc1_w + l * 256 * 128 + tid;
#pragma unroll 8
        for (int i = 0; i < 256; ++i) acc = fmaf(feat[i], W[i * 128], acc);
        float av = a4[l];
        h1[tid] = prelu(acc, av);
    }
    __syncthreads();
    if (tid < 64) {
        float acc = fc2_b[l * 64 + tid];
        const float* W = fc2_w + l * 128 * 64 + tid;
#pragma unroll 8
        for (int i = 0; i < 128; ++i) acc = fmaf(h1[i], W[i * 64], acc);
        float av = a5[l];
        h2[tid] = prelu(acc, av);
    }
    __syncthreads();
    if (tid < 4) {
        float acc = fc3_b[l * 4 + tid];
        const float* W = fc3_w + l * 64 * 4 + tid;
#pragma unroll
        for (int i = 0; i < 64; ++i) acc = fmaf(h2[i], W[i * 4], acc);
        out[bl * 4 + tid] = acc;
    }
}

// ---------------------------------------------------------------------------
extern "C" void kernel_launch(void* const* d_in, const int* in_sizes, int n_in,
                              void* d_out, int out_size) {
    const float* x     = (const float*)d_in[0];
    const float* w0    = (const float*)d_in[1];
    const float* b0    = (const float*)d_in[2];
    const float* w1    = (const float*)d_in[3];
    const float* b1    = (const float*)d_in[4];
    const float* w2    = (const float*)d_in[5];
    const float* b2    = (const float*)d_in[6];
    const float* w3    = (const float*)d_in[7];
    const float* b3    = (const float*)d_in[8];
    const float* a0    = (const float*)d_in[9];
    const float* a1    = (const float*)d_in[10];
    const float* a2    = (const float*)d_in[11];
    const float* a3    = (const float*)d_in[12];
    const float* fc1_w = (const float*)d_in[13];
    const float* fc1_b = (const float*)d_in[14];
    const float* a4    = (const float*)d_in[15];
    const float* fc2_w = (const float*)d_in[16];
    const float* fc2_b = (const float*)d_in[17];
    const float* a5    = (const float*)d_in[18];
    const float* fc3_w = (const float*)d_in[19];
    const float* fc3_b = (const float*)d_in[20];
    float* out = (float*)d_out;

    const int smem0 = (8464 + 3232) * 4;
    const int smem3 = (36928 + 8192) * 4;

    cudaFuncSetAttribute(k_conv0, cudaFuncAttributeMaxDynamicSharedMemorySize, smem0);
    cudaFuncSetAttribute(k_conv1_mma, cudaFuncAttributeMaxDynamicSharedMemorySize, SMEM_C1);
    cudaFuncSetAttribute(k_conv2_mma, cudaFuncAttributeMaxDynamicSharedMemorySize, SMEM_C2);
    cudaFuncSetAttribute(k_conv3, cudaFuncAttributeMaxDynamicSharedMemorySize, smem3);

    k_w1prep<<<dim3(25, 4), 512>>>(w1);
    k_w2prep<<<dim3(16, 4), 1024>>>(w2);
    k_conv0<<<BL, 224, smem0>>>(x, w0, b0, a0);
    k_conv1_mma<<<BL, 224, SMEM_C1>>>(b1, a1);
    k_conv2_mma<<<BL / 2, 256, SMEM_C2>>>(b2, a2);
    k_conv3<<<BL / 8, 256, smem3>>>(w3, b3, a3);
    k_fc<<<BL, 128>>>(fc1_w, fc1_b, a4, fc2_w, fc2_b, a5, fc3_w, fc3_b, out);
}

// round 7
// speedup vs baseline: 1.6861x; 1.3744x over previous
#include <cuda_runtime.h>
#include <cuda_bf16.h>
#include <cstdint>

// ---------------------------------------------------------------------------
// DQN_19198503813318 — R7: conv1+conv2 via mma.sync m16n8k16 bf16 (hi/lo x3).
// Activations pre-packed in SMEM as bf16x2 channel pairs (hi & lo planes);
// hot loop is pure LDS + MMA. conv0/conv3/fc scalar.
// ---------------------------------------------------------------------------

#define BL 3072

__device__ float g_s0[BL * 32 * 21 * 21];   // after stage0 (planar)
__device__ float g_s1[BL * 32 * 9 * 9];     // after stage1
__device__ float g_s2[BL * 64 * 4 * 4];     // after stage2
__device__ float g_s3[BL * 256];            // flattened features
// conv1 W frags: [p][g][lane][nf] -> uint4 (hi_b0, hi_b1, lo_b0, lo_b1)
__device__ uint4 g_w1B[25 * 2 * 32 * 4];
// conv2 W frags: [p][g][lane][nf 0..7] -> uint4
__device__ uint4 g_w2B[16 * 2 * 32 * 8];

__device__ __forceinline__ float prelu(float v, float a) {
    return v >= 0.0f ? v : a * v;
}

// pack two f32 -> bf16x2 (vlo -> low half, vhi -> high half)
__device__ __forceinline__ uint32_t bf16pack(float vlo, float vhi) {
    uint32_t r;
    asm("cvt.rn.bf16x2.f32 %0, %1, %2;" : "=r"(r) : "f"(vhi), "f"(vlo));
    return r;
}

__device__ __forceinline__ void mma_bf16(float4& d,
                                         uint32_t a0, uint32_t a1, uint32_t a2, uint32_t a3,
                                         uint32_t b0, uint32_t b1) {
    asm volatile(
        "mma.sync.aligned.m16n8k16.row.col.f32.bf16.bf16.f32 "
        "{%0,%1,%2,%3}, {%4,%5,%6,%7}, {%8,%9}, {%0,%1,%2,%3};"
        : "+f"(d.x), "+f"(d.y), "+f"(d.z), "+f"(d.w)
        : "r"(a0), "r"(a1), "r"(a2), "r"(a3), "r"(b0), "r"(b1));
}

// split v into bf16 hi/lo pair words given two channel values
__device__ __forceinline__ void split2(float v0, float v1, uint32_t& hp, uint32_t& lp) {
    hp = bf16pack(v0, v1);
    float r0 = __uint_as_float(hp << 16);
    float r1 = __uint_as_float(hp & 0xffff0000u);
    lp = bf16pack(v0 - r0, v1 - r1);
}

// ---------------------------------------------------------------------------
// conv1 weight prep: grid=(25,2)[p,g], block=128 (lane=tid&31, nf=tid>>5)
//   n = nf*8 + (lane>>2); ic0 = g*16 + 2*(lane&3); b0=(ic0,ic0+1), b1=(+8,+9)
// ---------------------------------------------------------------------------
__global__ void k_w1prep(const float* __restrict__ w1) {
    const int p    = blockIdx.x;
    const int g    = blockIdx.y;
    const int lane = threadIdx.x & 31;
    const int nf   = threadIdx.x >> 5;
    const int n    = nf * 8 + (lane >> 2);
    const int ic0  = g * 16 + 2 * (lane & 3);
    float v0 = w1[n * 800 + ic0 * 25 + p];
    float v1 = w1[n * 800 + (ic0 + 1) * 25 + p];
    float v8 = w1[n * 800 + (ic0 + 8) * 25 + p];
    float v9 = w1[n * 800 + (ic0 + 9) * 25 + p];
    uint32_t hb0, lb0, hb1, lb1;
    split2(v0, v1, hb0, lb0);
    split2(v8, v9, hb1, lb1);
    g_w1B[((p * 2 + g) * 32 + lane) * 4 + nf] = make_uint4(hb0, hb1, lb0, lb1);
}

// ---------------------------------------------------------------------------
// conv2 weight prep: grid=(16,2)[p,g], block=256 (lane=tid&31, nf=tid>>5 0..7)
// ---------------------------------------------------------------------------
__global__ void k_w2prep(const float* __restrict__ w2) {
    const int p    = blockIdx.x;
    const int g    = blockIdx.y;
    const int lane = threadIdx.x & 31;
    const int nf   = threadIdx.x >> 5;
    const int n    = nf * 8 + (lane >> 2);
    const int ic0  = g * 16 + 2 * (lane & 3);
    float v0 = w2[n * 512 + ic0 * 16 + p];
    float v1 = w2[n * 512 + (ic0 + 1) * 16 + p];
    float v8 = w2[n * 512 + (ic0 + 8) * 16 + p];
    float v9 = w2[n * 512 + (ic0 + 9) * 16 + p];
    uint32_t hb0, lb0, hb1, lb1;
    split2(v0, v1, hb0, lb0);
    split2(v8, v9, hb1, lb1);
    g_w2B[((p * 2 + g) * 32 + lane) * 8 + nf] = make_uint4(hb0, hb1, lb0, lb1);
}

// ---------------------------------------------------------------------------
// Stage 1 (mma bf16): conv(32->32,5x5,pad1)+prelu+pool2. grid=BL, block=224.
// sHi/sLo: 22x22 padded rows x 16 bf16x2 pairs, row stride 20 (conflict-free).
// ---------------------------------------------------------------------------
#define C1_STR  20
#define C1_HALF (484 * C1_STR)          // 9680 u32 per plane
#define SMEM_C1 (2 * C1_HALF * 4)       // 77440 B

__global__ void __launch_bounds__(224, 2)
k_conv1_mma(const float* __restrict__ b, const float* __restrict__ ap) {
    extern __shared__ uint32_t sm1[];
    uint32_t* sHi = sm1;
    uint32_t* sLo = sm1 + C1_HALF;
    const int tid = threadIdx.x;
    const int wid = tid >> 5;
    const int lid = tid & 31;
    const int bl  = blockIdx.x;

    for (int i = tid; i < 2 * C1_HALF; i += 224) sm1[i] = 0u;
    __syncthreads();
    const float* src = g_s0 + bl * 14112;
    for (int i = tid; i < 7056; i += 224) {
        int pr  = i / 441;          // channel pair 0..15
        int pix = i - pr * 441;
        int y   = pix / 21;
        int x   = pix - y * 21;
        float v0 = src[(2 * pr) * 441 + pix];
        float v1 = src[(2 * pr + 1) * 441 + pix];
        uint32_t hp, lp;
        split2(v0, v1, hp, lp);
        int idx = ((y + 1) * 22 + (x + 1)) * C1_STR + pr;
        sHi[idx] = hp;
        sLo[idx] = lp;
    }
    __syncthreads();

    int base[3][2];
#pragma unroll
    for (int t = 0; t < 3; ++t) {
#pragma unroll
        for (int j = 0; j < 2; ++j) {
            int m  = (wid * 3 + t) * 16 + (lid >> 2) + j * 8;
            int mm = m < 324 ? m : 0;
            int ym = mm / 18;
            int xm = mm - ym * 18;
            base[t][j] = (ym * 22 + xm) * C1_STR;
        }
    }

    float4 acc[3][4];
#pragma unroll
    for (int t = 0; t < 3; ++t)
#pragma unroll
        for (int nf = 0; nf < 4; ++nf)
            acc[t][nf] = make_float4(0.f, 0.f, 0.f, 0.f);

    const int cb = lid & 3;
    for (int p = 0; p < 25; ++p) {
        const int ky = p / 5;
        const int kx = p - ky * 5;
        const int off = (ky * 22 + kx) * C1_STR;
#pragma unroll
        for (int g = 0; g < 2; ++g) {
            const uint4* gB = g_w1B + ((p * 2 + g) * 32 + lid) * 4;
            uint4 B0 = gB[0], B1 = gB[1], B2 = gB[2], B3 = gB[3];
            const int c = g * 8 + cb;
#pragma unroll
            for (int t = 0; t < 3; ++t) {
                const int i0 = base[t][0] + off + c;
                const int i1 = base[t][1] + off + c;
                uint32_t ha0 = sHi[i0], ha1 = sHi[i1];
                uint32_t ha2 = sHi[i0 + 4], ha3 = sHi[i1 + 4];
                uint32_t la0 = sLo[i0], la1 = sLo[i1];
                uint32_t la2 = sLo[i0 + 4], la3 = sLo[i1 + 4];
                mma_bf16(acc[t][0], ha0, ha1, ha2, ha3, B0.x, B0.y);
                mma_bf16(acc[t][1], ha0, ha1, ha2, ha3, B1.x, B1.y);
                mma_bf16(acc[t][2], ha0, ha1, ha2, ha3, B2.x, B2.y);
                mma_bf16(acc[t][3], ha0, ha1, ha2, ha3, B3.x, B3.y);
                mma_bf16(acc[t][0], la0, la1, la2, la3, B0.x, B0.y);
                mma_bf16(acc[t][1], la0, la1, la2, la3, B1.x, B1.y);
                mma_bf16(acc[t][2], la0, la1, la2, la3, B2.x, B2.y);
                mma_bf16(acc[t][3], la0, la1, la2, la3, B3.x, B3.y);
                mma_bf16(acc[t][0], ha0, ha1, ha2, ha3, B0.z, B0.w);
                mma_bf16(acc[t][1], ha0, ha1, ha2, ha3, B1.z, B1.w);
                mma_bf16(acc[t][2], ha0, ha1, ha2, ha3, B2.z, B2.w);
                mma_bf16(acc[t][3], ha0, ha1, ha2, ha3, B3.z, B3.w);
            }
        }
    }
    __syncthreads();   // reuse smem as fp32 stage (336 rows x stride 33 = 11088 <= 19360)

    const float a = *ap;
    float* stage = (float*)sm1;
    {
        const int r0 = (wid * 3) * 16 + (lid >> 2);
        const int oc0 = 2 * (lid & 3);
#pragma unroll
        for (int t = 0; t < 3; ++t) {
            int ra = r0 + t * 16;
            int rb = ra + 8;
#pragma unroll
            for (int nf = 0; nf < 4; ++nf) {
                int ca = nf * 8 + oc0;
                float ba = b[ca], bb = b[ca + 1];
                stage[ra * 33 + ca]     = prelu(acc[t][nf].x + ba, a);
                stage[ra * 33 + ca + 1] = prelu(acc[t][nf].y + bb, a);
                stage[rb * 33 + ca]     = prelu(acc[t][nf].z + ba, a);
                stage[rb * 33 + ca + 1] = prelu(acc[t][nf].w + bb, a);
            }
        }
    }
    __syncthreads();

    float* out = g_s1 + bl * 2592;
    for (int i = tid; i < 2592; i += 224) {
        int oc = i / 81;
        int pp = i - oc * 81;
        int py = pp / 9;
        int px = pp - py * 9;
        int m00 = (2 * py) * 18 + 2 * px;
        float v = fmaxf(fmaxf(stage[m00 * 33 + oc],        stage[(m00 + 1) * 33 + oc]),
                        fmaxf(stage[(m00 + 18) * 33 + oc], stage[(m00 + 19) * 33 + oc]));
        out[i] = v;
    }
}

// ---------------------------------------------------------------------------
// Stage 2 (mma bf16): conv(32->64,4x4,pad1)+prelu+pool2. grid=BL/2, block=256.
// 2 images/CTA: M=128 (8 warps x 16 rows), N=64 (8 nf), K=16 pos x 32 ic.
// ---------------------------------------------------------------------------
#define C2_STR  20
#define C2_IMGW (121 * C2_STR)              // 2420 u32 per image per plane
#define C2_HALF (2 * C2_IMGW)               // 4840
#define SMEM_C2 (2 * C2_HALF * 4)           // 38720 B

__global__ void __launch_bounds__(256, 2)
k_conv2_mma(const float* __restrict__ b, const float* __restrict__ ap) {
    extern __shared__ uint32_t sm2[];
    uint32_t* sHi = sm2;
    uint32_t* sLo = sm2 + C2_HALF;
    const int tid = threadIdx.x;
    const int wid = tid >> 5;
    const int lid = tid & 31;
    const int bl  = blockIdx.x;             // image pair

    for (int i = tid; i < 2 * C2_HALF; i += 256) sm2[i] = 0u;
    __syncthreads();
    const float* src = g_s1 + bl * 2 * 2592;
    for (int i = tid; i < 2592; i += 256) {
        int img = i / 1296;
        int r   = i - img * 1296;
        int pr  = r / 81;
        int pix = r - pr * 81;
        int y   = pix / 9;
        int x   = pix - y * 9;
        float v0 = src[img * 2592 + (2 * pr) * 81 + pix];
        float v1 = src[img * 2592 + (2 * pr + 1) * 81 + pix];
        uint32_t hp, lp;
        split2(v0, v1, hp, lp);
        int idx = img * C2_IMGW + ((y + 1) * 11 + (x + 1)) * C2_STR + pr;
        sHi[idx] = hp;
        sLo[idx] = lp;
    }
    __syncthreads();

    const int img = wid >> 2;
    int base[2];
#pragma unroll
    for (int j = 0; j < 2; ++j) {
        int m   = wid * 16 + (lid >> 2) + j * 8;
        int pix = m & 63;
        int oy  = pix >> 3;
        int ox  = pix & 7;
        base[j] = img * C2_IMGW + (oy * 11 + ox) * C2_STR;
    }

    float4 acc[8];
#pragma unroll
    for (int nf = 0; nf < 8; ++nf) acc[nf] = make_float4(0.f, 0.f, 0.f, 0.f);

    const int cb = lid & 3;
    for (int p = 0; p < 16; ++p) {
        const int off = ((p >> 2) * 11 + (p & 3)) * C2_STR;
#pragma unroll
        for (int g = 0; g < 2; ++g) {
            const uint4* gB = g_w2B + ((p * 2 + g) * 32 + lid) * 8;
            const int c  = g * 8 + cb;
            const int i0 = base[0] + off + c;
            const int i1 = base[1] + off + c;
            uint32_t ha0 = sHi[i0], ha1 = sHi[i1];
            uint32_t ha2 = sHi[i0 + 4], ha3 = sHi[i1 + 4];
            uint32_t la0 = sLo[i0], la1 = sLo[i1];
            uint32_t la2 = sLo[i0 + 4], la3 = sLo[i1 + 4];
#pragma unroll
            for (int nf = 0; nf < 8; ++nf) {
                uint4 Bv = gB[nf];
                mma_bf16(acc[nf], ha0, ha1, ha2, ha3, Bv.x, Bv.y);
                mma_bf16(acc[nf], la0, la1, la2, la3, Bv.x, Bv.y);
                mma_bf16(acc[nf], ha0, ha1, ha2, ha3, Bv.z, Bv.w);
            }
        }
    }
    __syncthreads();   // reuse smem as fp32 stage: 128 rows x stride 65 = 8320 <= 9680

    const float a = *ap;
    float* stage = (float*)sm2;
    {
        const int r0  = wid * 16 + (lid >> 2);
        const int oc0 = 2 * (lid & 3);
#pragma unroll
        for (int nf = 0; nf < 8; ++nf) {
            int ca = nf * 8 + oc0;
            float ba = b[ca], bb = b[ca + 1];
            stage[r0 * 65 + ca]           = prelu(acc[nf].x + ba, a);
            stage[r0 * 65 + ca + 1]       = prelu(acc[nf].y + bb, a);
            stage[(r0 + 8) * 65 + ca]     = prelu(acc[nf].z + ba, a);
            stage[(r0 + 8) * 65 + ca + 1] = prelu(acc[nf].w + bb, a);
        }
    }
    __syncthreads();

    for (int i = tid; i < 2048; i += 256) {
        int im  = i >> 10;
        int rem = i & 1023;
        int oc  = rem >> 4;
        int pp  = rem & 15;
        int py  = pp >> 2;
        int px  = pp & 3;
        int m00 = im * 64 + (2 * py) * 8 + 2 * px;
        float v = fmaxf(fmaxf(stage[m00 * 65 + oc],       stage[(m00 + 1) * 65 + oc]),
                        fmaxf(stage[(m00 + 8) * 65 + oc], stage[(m00 + 9) * 65 + oc]));
        g_s2[((bl * 2 + im) * 64 + oc) * 16 + py * 4 + px] = v;
    }
}

// ---------------------------------------------------------------------------
// Stage 0 (scalar): conv(4->32,5x5,pad1)+prelu+pool2
// ---------------------------------------------------------------------------
__global__ void k_conv0(const float* __restrict__ x,
                        const float* __restrict__ w,
                        const float* __restrict__ b,
                        const float* __restrict__ ap) {
    extern __shared__ float smem[];
    float* sIn = smem;          // 4*46*46 = 8464
    float* sW  = smem + 8464;   // 32*101  = 3232
    const int bl  = blockIdx.x;
    const int tid = threadIdx.x;

    for (int i = tid; i < 8464; i += 224) sIn[i] = 0.0f;
    __syncthreads();
    const float* xb = x + bl * 8100;
    for (int i = tid; i < 8100; i += 224) {
        int ic = i / 2025;
        int r  = (i / 45) % 45;
        int c  = i % 45;
        sIn[ic * 2116 + (r + 1) * 46 + (c + 1)] = xb[i];
    }
    for (int k = tid; k < 3200; k += 224) {
        int oc = k / 100;
        sW[oc * 101 + (k % 100)] = w[k];
    }
    __syncthreads();

    const int oc = tid & 31;
    const int g  = tid >> 5;
    const float bias = b[oc];
    const float a = *ap;
    const float* wB = sW + oc * 101;

    for (int py = 0; py < 21; ++py) {
        float accA[6], accB[6];
#pragma unroll
        for (int j = 0; j < 6; ++j) { accA[j] = bias; accB[j] = bias; }
        const int y0 = 2 * py;
        for (int ic = 0; ic < 4; ++ic) {
            const float* inC = sIn + ic * 2116;
#pragma unroll
            for (int ky = 0; ky < 5; ++ky) {
                const float* r0 = inC + (y0 + ky) * 46 + 6 * g;
                const float* r1 = r0 + 46;
                float ra[10], rb[10];
#pragma unroll
                for (int j = 0; j < 10; ++j) { ra[j] = r0[j]; rb[j] = r1[j]; }
                const float* wv = wB + ic * 25 + ky * 5;
#pragma unroll
                for (int kx = 0; kx < 5; ++kx) {
                    float wk = wv[kx];
#pragma unroll
                    for (int j = 0; j < 6; ++j) {
                        accA[j] = fmaf(ra[j + kx], wk, accA[j]);
                        accB[j] = fmaf(rb[j + kx], wk, accB[j]);
                    }
                }
            }
        }
        float* o = g_s0 + ((bl * 32 + oc) * 21 + py) * 21 + 3 * g;
#pragma unroll
        for (int u = 0; u < 3; ++u) {
            float v0 = prelu(accA[2 * u], a);
            float v1 = prelu(accA[2 * u + 1], a);
            float v2 = prelu(accB[2 * u], a);
            float v3 = prelu(accB[2 * u + 1], a);
            o[u] = fmaxf(fmaxf(v0, v1), fmaxf(v2, v3));
        }
    }
}

// ---------------------------------------------------------------------------
// Stage 3 (scalar): conv(64->64,3x3,pad0)+prelu+flatten
// ---------------------------------------------------------------------------
__global__ void k_conv3(const float* __restrict__ w,
                        const float* __restrict__ b,
                        const float* __restrict__ ap) {
    extern __shared__ float smem[];
    float* sW  = smem;             // 64*577 = 36928
    float* sIn = smem + 36928;     // 8*1024 = 8192
    const int tid = threadIdx.x;
    const int bl0 = blockIdx.x * 8;

    for (int k = tid; k < 64 * 576; k += 256) {
        int oc = k / 576;
        sW[oc * 577 + (k % 576)] = w[k];
    }
    const float* src = g_s2 + bl0 * 1024;
    for (int i = tid; i < 8192; i += 256) sIn[i] = src[i];
    __syncthreads();

    const int oc  = tid >> 2;
    const int pos = tid & 3;
    const int yy  = pos >> 1;
    const int xx  = pos & 1;
    const float bias = b[oc];
    const float a = *ap;

    float acc[8];
#pragma unroll
    for (int i = 0; i < 8; ++i) acc[i] = bias;

    for (int ic = 0; ic < 64; ++ic) {
        const float* wv = sW + oc * 577 + ic * 9;
        float wr[9];
#pragma unroll
        for (int j = 0; j < 9; ++j) wr[j] = wv[j];
#pragma unroll
        for (int img = 0; img < 8; ++img) {
            const float* ip = sIn + img * 1024 + ic * 16;
#pragma unroll
            for (int ky = 0; ky < 3; ++ky)
#pragma unroll
                for (int kx = 0; kx < 3; ++kx)
                    acc[img] = fmaf(ip[(yy + ky) * 4 + (xx + kx)], wr[ky * 3 + kx], acc[img]);
        }
    }
#pragma unroll
    for (int img = 0; img < 8; ++img) {
        g_s3[(bl0 + img) * 256 + oc * 4 + pos] = prelu(acc[img], a);
    }
}

// ---------------------------------------------------------------------------
// FC heads
// ---------------------------------------------------------------------------
__global__ void k_fc(const float* __restrict__ fc1_w, const float* __restrict__ fc1_b,
                     const float* __restrict__ a4,
                     const float* __restrict__ fc2_w, const float* __restrict__ fc2_b,
                     const float* __restrict__ a5,
                     const float* __restrict__ fc3_w, const float* __restrict__ fc3_b,
                     float* __restrict__ out) {
    __shared__ float feat[256];
    __shared__ float h1[128];
    __shared__ float h2[64];
    const int bl  = blockIdx.x;
    const int l   = bl % 6;
    const int tid = threadIdx.x;

    feat[tid]       = g_s3[bl * 256 + tid];
    feat[tid + 128] = g_s3[bl * 256 + 128 + tid];
    __syncthreads();

    {
        float acc = fc1_b[l * 128 + tid];
        const float* W = fc1_w + l * 256 * 128 + tid;
#pragma unroll 8
        for (int i = 0; i < 256; ++i) acc = fmaf(feat[i], W[i * 128], acc);
        float av = a4[l];
        h1[tid] = prelu(acc, av);
    }
    __syncthreads();
    if (tid < 64) {
        float acc = fc2_b[l * 64 + tid];
        const float* W = fc2_w + l * 128 * 64 + tid;
#pragma unroll 8
        for (int i = 0; i < 128; ++i) acc = fmaf(h1[i], W[i * 64], acc);
        float av = a5[l];
        h2[tid] = prelu(acc, av);
    }
    __syncthreads();
    if (tid < 4) {
        float acc = fc3_b[l * 4 + tid];
        const float* W = fc3_w + l * 64 * 4 + tid;
#pragma unroll
        for (int i = 0; i < 64; ++i) acc = fmaf(h2[i], W[i * 4], acc);
        out[bl * 4 + tid] = acc;
    }
}

// ---------------------------------------------------------------------------
extern "C" void kernel_launch(void* const* d_in, const int* in_sizes, int n_in,
                              void* d_out, int out_size) {
    const float* x     = (const float*)d_in[0];
    const float* w0    = (const float*)d_in[1];
    const float* b0    = (const float*)d_in[2];
    const float* w1    = (const float*)d_in[3];
    const float* b1    = (const float*)d_in[4];
    const float* w2    = (const float*)d_in[5];
    const float* b2    = (const float*)d_in[6];
    const float* w3    = (const float*)d_in[7];
    const float* b3    = (const float*)d_in[8];
    const float* a0    = (const float*)d_in[9];
    const float* a1    = (const float*)d_in[10];
    const float* a2    = (const float*)d_in[11];
    const float* a3    = (const float*)d_in[12];
    const float* fc1_w = (const float*)d_in[13];
    const float* fc1_b = (const float*)d_in[14];
    const float* a4    = (const float*)d_in[15];
    const float* fc2_w = (const float*)d_in[16];
    const float* fc2_b = (const float*)d_in[17];
    const float* a5    = (const float*)d_in[18];
    const float* fc3_w = (const float*)d_in[19];
    const float* fc3_b = (const float*)d_in[20];
    float* out = (float*)d_out;

    const int smem0 = (8464 + 3232) * 4;
    const int smem3 = (36928 + 8192) * 4;

    cudaFuncSetAttribute(k_conv0, cudaFuncAttributeMaxDynamicSharedMemorySize, smem0);
    cudaFuncSetAttribute(k_conv1_mma, cudaFuncAttributeMaxDynamicSharedMemorySize, SMEM_C1);
    cudaFuncSetAttribute(k_conv2_mma, cudaFuncAttributeMaxDynamicSharedMemorySize, SMEM_C2);
    cudaFuncSetAttribute(k_conv3, cudaFuncAttributeMaxDynamicSharedMemorySize, smem3);

    k_w1prep<<<dim3(25, 2), 128>>>(w1);
    k_w2prep<<<dim3(16, 2), 256>>>(w2);
    k_conv0<<<BL, 224, smem0>>>(x, w0, b0, a0);
    k_conv1_mma<<<BL, 224, SMEM_C1>>>(b1, a1);
    k_conv2_mma<<<BL / 2, 256, SMEM_C2>>>(b2, a2);
    k_conv3<<<BL / 8, 256, smem3>>>(w3, b3, a3);
    k_fc<<<BL, 128>>>(fc1_w, fc1_b, a4, fc2_w, fc2_b, a5, fc3_w, fc3_b, out);
}

// round 8
// speedup vs baseline: 1.6921x; 1.0036x over previous
#include <cuda_runtime.h>
#include <cuda_bf16.h>
#include <cstdint>

// ---------------------------------------------------------------------------
// DQN_19198503813318 — R8: conv0+conv1+conv2 via mma.sync m16n8k16 bf16
// (hi/lo x3). conv0 uses pooled-quad-major M ordering -> shfl max-pool.
// conv3/fc scalar.
// ---------------------------------------------------------------------------

#define BL 3072

__device__ float g_s0[BL * 32 * 21 * 21];   // after stage0 (planar)
__device__ float g_s1[BL * 32 * 9 * 9];     // after stage1
__device__ float g_s2[BL * 64 * 4 * 4];     // after stage2
__device__ float g_s3[BL * 256];            // flattened features
// conv0 W frags: [c 0..6][lane][nf 0..3] -> uint4 (hi_b0, hi_b1, lo_b0, lo_b1)
__device__ uint4 g_w0B[7 * 32 * 4];
// conv1 W frags: [p][g][lane][nf]
__device__ uint4 g_w1B[25 * 2 * 32 * 4];
// conv2 W frags: [p][g][lane][nf 0..7]
__device__ uint4 g_w2B[16 * 2 * 32 * 8];

__device__ __forceinline__ float prelu(float v, float a) {
    return v >= 0.0f ? v : a * v;
}

__device__ __forceinline__ uint32_t bf16pack(float vlo, float vhi) {
    uint32_t r;
    asm("cvt.rn.bf16x2.f32 %0, %1, %2;" : "=r"(r) : "f"(vhi), "f"(vlo));
    return r;
}

__device__ __forceinline__ void mma_bf16(float4& d,
                                         uint32_t a0, uint32_t a1, uint32_t a2, uint32_t a3,
                                         uint32_t b0, uint32_t b1) {
    asm volatile(
        "mma.sync.aligned.m16n8k16.row.col.f32.bf16.bf16.f32 "
        "{%0,%1,%2,%3}, {%4,%5,%6,%7}, {%8,%9}, {%0,%1,%2,%3};"
        : "+f"(d.x), "+f"(d.y), "+f"(d.z), "+f"(d.w)
        : "r"(a0), "r"(a1), "r"(a2), "r"(a3), "r"(b0), "r"(b1));
}

__device__ __forceinline__ void split2(float v0, float v1, uint32_t& hp, uint32_t& lp) {
    hp = bf16pack(v0, v1);
    float r0 = __uint_as_float(hp << 16);
    float r1 = __uint_as_float(hp & 0xffff0000u);
    lp = bf16pack(v0 - r0, v1 - r1);
}

// ---------------------------------------------------------------------------
// conv0 weight prep: grid=7 [chunk], block=128 (lane=tid&31, nf=tid>>5)
//   chunk c = positions 4c..4c+3 x 4 ic. pair pr: pos=4c+(pr>>1), icp=pr&1.
//   lane pair cb=lane&3 -> b0; cb+4 -> b1. n = nf*8 + (lane>>2).
// ---------------------------------------------------------------------------
__global__ void k_w0prep(const float* __restrict__ w0) {
    const int c    = blockIdx.x;
    const int lane = threadIdx.x & 31;
    const int nf   = threadIdx.x >> 5;
    const int n    = nf * 8 + (lane >> 2);
    const int cb   = lane & 3;
    const int icp  = cb & 1;
    const int p0   = 4 * c + (cb >> 1);
    const int p2   = p0 + 2;
    float v0 = 0.f, v1 = 0.f, v2 = 0.f, v3 = 0.f;
    if (p0 < 25) {
        v0 = w0[n * 100 + (2 * icp) * 25 + p0];
        v1 = w0[n * 100 + (2 * icp + 1) * 25 + p0];
    }
    if (p2 < 25) {
        v2 = w0[n * 100 + (2 * icp) * 25 + p2];
        v3 = w0[n * 100 + (2 * icp + 1) * 25 + p2];
    }
    uint32_t hb0, lb0, hb1, lb1;
    split2(v0, v1, hb0, lb0);
    split2(v2, v3, hb1, lb1);
    g_w0B[(c * 32 + lane) * 4 + nf] = make_uint4(hb0, hb1, lb0, lb1);
}

// ---------------------------------------------------------------------------
// conv1 weight prep: grid=(25,2)[p,g], block=128
// ---------------------------------------------------------------------------
__global__ void k_w1prep(const float* __restrict__ w1) {
    const int p    = blockIdx.x;
    const int g    = blockIdx.y;
    const int lane = threadIdx.x & 31;
    const int nf   = threadIdx.x >> 5;
    const int n    = nf * 8 + (lane >> 2);
    const int ic0  = g * 16 + 2 * (lane & 3);
    float v0 = w1[n * 800 + ic0 * 25 + p];
    float v1 = w1[n * 800 + (ic0 + 1) * 25 + p];
    float v8 = w1[n * 800 + (ic0 + 8) * 25 + p];
    float v9 = w1[n * 800 + (ic0 + 9) * 25 + p];
    uint32_t hb0, lb0, hb1, lb1;
    split2(v0, v1, hb0, lb0);
    split2(v8, v9, hb1, lb1);
    g_w1B[((p * 2 + g) * 32 + lane) * 4 + nf] = make_uint4(hb0, hb1, lb0, lb1);
}

// ---------------------------------------------------------------------------
// conv2 weight prep: grid=(16,2)[p,g], block=256
// ---------------------------------------------------------------------------
__global__ void k_w2prep(const float* __restrict__ w2) {
    const int p    = blockIdx.x;
    const int g    = blockIdx.y;
    const int lane = threadIdx.x & 31;
    const int nf   = threadIdx.x >> 5;
    const int n    = nf * 8 + (lane >> 2);
    const int ic0  = g * 16 + 2 * (lane & 3);
    float v0 = w2[n * 512 + ic0 * 16 + p];
    float v1 = w2[n * 512 + (ic0 + 1) * 16 + p];
    float v8 = w2[n * 512 + (ic0 + 8) * 16 + p];
    float v9 = w2[n * 512 + (ic0 + 9) * 16 + p];
    uint32_t hb0, lb0, hb1, lb1;
    split2(v0, v1, hb0, lb0);
    split2(v8, v9, hb1, lb1);
    g_w2B[((p * 2 + g) * 32 + lane) * 8 + nf] = make_uint4(hb0, hb1, lb0, lb1);
}

// ---------------------------------------------------------------------------
// Stage 0 (mma bf16): conv(4->32,5x5,pad1)+prelu+pool2. grid=BL, block=224.
// M pooled-quad-major: m = quad*4 + sub; quad = py*21+px; y=2py+(sub>>1),
// x=2px+(sub&1). Tile=16 m = 4 quads; pooling via shfl_xor(4),(8).
// smem: sHi/sLo 47x47 padded rows x 2 channel-pair words.
// ---------------------------------------------------------------------------
#define C0_HALF (47 * 47 * 2)           // 4418 u32 per plane
#define SMEM_C0 (2 * C0_HALF * 4)       // 35344 B

__global__ void __launch_bounds__(224, 3)
k_conv0_mma(const float* __restrict__ x,
            const float* __restrict__ b, const float* __restrict__ ap) {
    extern __shared__ uint32_t sm0[];
    uint32_t* sHi = sm0;
    uint32_t* sLo = sm0 + C0_HALF;
    const int tid = threadIdx.x;
    const int wid = tid >> 5;
    const int lid = tid & 31;
    const int bl  = blockIdx.x;

    for (int i = tid; i < 2 * C0_HALF; i += 224) sm0[i] = 0u;
    __syncthreads();
    const float* xb = x + bl * 8100;
    for (int i = tid; i < 4050; i += 224) {
        int pix = i >> 1;
        int pr  = i & 1;
        int y   = pix / 45;
        int xx  = pix - y * 45;
        float v0 = xb[(2 * pr) * 2025 + pix];
        float v1 = xb[(2 * pr + 1) * 2025 + pix];
        uint32_t hp, lp;
        split2(v0, v1, hp, lp);
        int idx = ((y + 1) * 47 + (xx + 1)) * 2 + pr;
        sHi[idx] = hp;
        sLo[idx] = lp;
    }
    __syncthreads();

    const int cb  = lid & 3;
    const int icp = cb & 1;
    // per-chunk position offsets (lane-dependent)
    int off0[7], off2[7];
#pragma unroll
    for (int c = 0; c < 7; ++c) {
        int p0 = 4 * c + (cb >> 1);
        int p2 = p0 + 2;
        if (p0 > 24) p0 = 24;
        if (p2 > 24) p2 = 24;
        off0[c] = ((p0 / 5) * 47 + (p0 % 5)) * 2 + icp;
        off2[c] = ((p2 / 5) * 47 + (p2 % 5)) * 2 + icp;
    }
    // bias per nf (2 oc per lane)
    float bx[4], by[4];
#pragma unroll
    for (int nf = 0; nf < 4; ++nf) {
        bx[nf] = b[nf * 8 + 2 * cb];
        by[nf] = b[nf * 8 + 2 * cb + 1];
    }
    const float a = *ap;
    float* out = g_s0 + bl * 14112;
    const bool wr = ((lid >> 2) & 3) == 0;
    const int qoff = (lid >= 16) ? 1 : 0;

    for (int t = 0; t < 16; ++t) {
        const int tt = wid * 16 + t;        // tile 0..111
        int rb0, rb1;
        {
            int m0 = tt * 16 + (lid >> 2);
            int m1 = m0 + 8;
            if (m0 >= 1764) m0 = 0;
            if (m1 >= 1764) m1 = 0;
            int q0 = m0 >> 2, s0 = m0 & 3;
            int q1 = m1 >> 2, s1 = m1 & 3;
            int y0 = 2 * (q0 / 21) + (s0 >> 1), x0 = 2 * (q0 % 21) + (s0 & 1);
            int y1 = 2 * (q1 / 21) + (s1 >> 1), x1 = 2 * (q1 % 21) + (s1 & 1);
            rb0 = (y0 * 47 + x0) * 2;
            rb1 = (y1 * 47 + x1) * 2;
        }
        float4 acc[4];
#pragma unroll
        for (int nf = 0; nf < 4; ++nf) acc[nf] = make_float4(0.f, 0.f, 0.f, 0.f);

#pragma unroll
        for (int c = 0; c < 7; ++c) {
            const uint4* gB = g_w0B + (c * 32 + lid) * 4;
            uint4 B0 = gB[0], B1 = gB[1], B2 = gB[2], B3 = gB[3];
            uint32_t ha0 = sHi[rb0 + off0[c]], ha1 = sHi[rb1 + off0[c]];
            uint32_t ha2 = sHi[rb0 + off2[c]], ha3 = sHi[rb1 + off2[c]];
            uint32_t la0 = sLo[rb0 + off0[c]], la1 = sLo[rb1 + off0[c]];
            uint32_t la2 = sLo[rb0 + off2[c]], la3 = sLo[rb1 + off2[c]];
            mma_bf16(acc[0], ha0, ha1, ha2, ha3, B0.x, B0.y);
            mma_bf16(acc[1], ha0, ha1, ha2, ha3, B1.x, B1.y);
            mma_bf16(acc[2], ha0, ha1, ha2, ha3, B2.x, B2.y);
            mma_bf16(acc[3], ha0, ha1, ha2, ha3, B3.x, B3.y);
            mma_bf16(acc[0], la0, la1, la2, la3, B0.x, B0.y);
            mma_bf16(acc[1], la0, la1, la2, la3, B1.x, B1.y);
            mma_bf16(acc[2], la0, la1, la2, la3, B2.x, B2.y);
            mma_bf16(acc[3], la0, la1, la2, la3, B3.x, B3.y);
            mma_bf16(acc[0], ha0, ha1, ha2, ha3, B0.z, B0.w);
            mma_bf16(acc[1], ha0, ha1, ha2, ha3, B1.z, B1.w);
            mma_bf16(acc[2], ha0, ha1, ha2, ha3, B2.z, B2.w);
            mma_bf16(acc[3], ha0, ha1, ha2, ha3, B3.z, B3.w);
        }
        // epilogue: bias+prelu, shfl max-pool over rows (lane bits 2,3)
        const int qA = tt * 4 + qoff;
        const int qB = qA + 2;
#pragma unroll
        for (int nf = 0; nf < 4; ++nf) {
            float vx = prelu(acc[nf].x + bx[nf], a);
            float vy = prelu(acc[nf].y + by[nf], a);
            float vz = prelu(acc[nf].z + bx[nf], a);
            float vw = prelu(acc[nf].w + by[nf], a);
            vx = fmaxf(vx, __shfl_xor_sync(0xffffffffu, vx, 4));
            vx = fmaxf(vx, __shfl_xor_sync(0xffffffffu, vx, 8));
            vy = fmaxf(vy, __shfl_xor_sync(0xffffffffu, vy, 4));
            vy = fmaxf(vy, __shfl_xor_sync(0xffffffffu, vy, 8));
            vz = fmaxf(vz, __shfl_xor_sync(0xffffffffu, vz, 4));
            vz = fmaxf(vz, __shfl_xor_sync(0xffffffffu, vz, 8));
            vw = fmaxf(vw, __shfl_xor_sync(0xffffffffu, vw, 4));
            vw = fmaxf(vw, __shfl_xor_sync(0xffffffffu, vw, 8));
            if (wr) {
                int oc0 = nf * 8 + 2 * cb;
                if (qA < 441) {
                    out[oc0 * 441 + qA]       = vx;
                    out[(oc0 + 1) * 441 + qA] = vy;
                }
                if (qB < 441) {
                    out[oc0 * 441 + qB]       = vz;
                    out[(oc0 + 1) * 441 + qB] = vw;
                }
            }
        }
    }
}

// ---------------------------------------------------------------------------
// Stage 1 (mma bf16): conv(32->32,5x5,pad1)+prelu+pool2. grid=BL, block=224.
// ---------------------------------------------------------------------------
#define C1_STR  20
#define C1_HALF (484 * C1_STR)          // 9680 u32 per plane
#define SMEM_C1 (2 * C1_HALF * 4)       // 77440 B

__global__ void __launch_bounds__(224, 2)
k_conv1_mma(const float* __restrict__ b, const float* __restrict__ ap) {
    extern __shared__ uint32_t sm1[];
    uint32_t* sHi = sm1;
    uint32_t* sLo = sm1 + C1_HALF;
    const int tid = threadIdx.x;
    const int wid = tid >> 5;
    const int lid = tid & 31;
    const int bl  = blockIdx.x;

    for (int i = tid; i < 2 * C1_HALF; i += 224) sm1[i] = 0u;
    __syncthreads();
    const float* src = g_s0 + bl * 14112;
    for (int i = tid; i < 7056; i += 224) {
        int pr  = i / 441;
        int pix = i - pr * 441;
        int y   = pix / 21;
        int x   = pix - y * 21;
        float v0 = src[(2 * pr) * 441 + pix];
        float v1 = src[(2 * pr + 1) * 441 + pix];
        uint32_t hp, lp;
        split2(v0, v1, hp, lp);
        int idx = ((y + 1) * 22 + (x + 1)) * C1_STR + pr;
        sHi[idx] = hp;
        sLo[idx] = lp;
    }
    __syncthreads();

    int base[3][2];
#pragma unroll
    for (int t = 0; t < 3; ++t) {
#pragma unroll
        for (int j = 0; j < 2; ++j) {
            int m  = (wid * 3 + t) * 16 + (lid >> 2) + j * 8;
            int mm = m < 324 ? m : 0;
            int ym = mm / 18;
            int xm = mm - ym * 18;
            base[t][j] = (ym * 22 + xm) * C1_STR;
        }
    }

    float4 acc[3][4];
#pragma unroll
    for (int t = 0; t < 3; ++t)
#pragma unroll
        for (int nf = 0; nf < 4; ++nf)
            acc[t][nf] = make_float4(0.f, 0.f, 0.f, 0.f);

    const int cb = lid & 3;
    for (int p = 0; p < 25; ++p) {
        const int ky = p / 5;
        const int kx = p - ky * 5;
        const int off = (ky * 22 + kx) * C1_STR;
#pragma unroll
        for (int g = 0; g < 2; ++g) {
            const uint4* gB = g_w1B + ((p * 2 + g) * 32 + lid) * 4;
            uint4 B0 = gB[0], B1 = gB[1], B2 = gB[2], B3 = gB[3];
            const int c = g * 8 + cb;
#pragma unroll
            for (int t = 0; t < 3; ++t) {
                const int i0 = base[t][0] + off + c;
                const int i1 = base[t][1] + off + c;
                uint32_t ha0 = sHi[i0], ha1 = sHi[i1];
                uint32_t ha2 = sHi[i0 + 4], ha3 = sHi[i1 + 4];
                uint32_t la0 = sLo[i0], la1 = sLo[i1];
                uint32_t la2 = sLo[i0 + 4], la3 = sLo[i1 + 4];
                mma_bf16(acc[t][0], ha0, ha1, ha2, ha3, B0.x, B0.y);
                mma_bf16(acc[t][1], ha0, ha1, ha2, ha3, B1.x, B1.y);
                mma_bf16(acc[t][2], ha0, ha1, ha2, ha3, B2.x, B2.y);
                mma_bf16(acc[t][3], ha0, ha1, ha2, ha3, B3.x, B3.y);
                mma_bf16(acc[t][0], la0, la1, la2, la3, B0.x, B0.y);
                mma_bf16(acc[t][1], la0, la1, la2, la3, B1.x, B1.y);
                mma_bf16(acc[t][2], la0, la1, la2, la3, B2.x, B2.y);
                mma_bf16(acc[t][3], la0, la1, la2, la3, B3.x, B3.y);
                mma_bf16(acc[t][0], ha0, ha1, ha2, ha3, B0.z, B0.w);
                mma_bf16(acc[t][1], ha0, ha1, ha2, ha3, B1.z, B1.w);
                mma_bf16(acc[t][2], ha0, ha1, ha2, ha3, B2.z, B2.w);
                mma_bf16(acc[t][3], ha0, ha1, ha2, ha3, B3.z, B3.w);
            }
        }
    }
    __syncthreads();   // reuse smem as fp32 stage (336 rows x stride 33)

    const float a = *ap;
    float* stage = (float*)sm1;
    {
        const int r0 = (wid * 3) * 16 + (lid >> 2);
        const int oc0 = 2 * (lid & 3);
#pragma unroll
        for (int t = 0; t < 3; ++t) {
            int ra = r0 + t * 16;
            int rb = ra + 8;
#pragma unroll
            for (int nf = 0; nf < 4; ++nf) {
                int ca = nf * 8 + oc0;
                float ba = b[ca], bb = b[ca + 1];
                stage[ra * 33 + ca]     = prelu(acc[t][nf].x + ba, a);
                stage[ra * 33 + ca + 1] = prelu(acc[t][nf].y + bb, a);
                stage[rb * 33 + ca]     = prelu(acc[t][nf].z + ba, a);
                stage[rb * 33 + ca + 1] = prelu(acc[t][nf].w + bb, a);
            }
        }
    }
    __syncthreads();

    float* out = g_s1 + bl * 2592;
    for (int i = tid; i < 2592; i += 224) {
        int oc = i / 81;
        int pp = i - oc * 81;
        int py = pp / 9;
        int px = pp - py * 9;
        int m00 = (2 * py) * 18 + 2 * px;
        float v = fmaxf(fmaxf(stage[m00 * 33 + oc],        stage[(m00 + 1) * 33 + oc]),
                        fmaxf(stage[(m00 + 18) * 33 + oc], stage[(m00 + 19) * 33 + oc]));
        out[i] = v;
    }
}

// ---------------------------------------------------------------------------
// Stage 2 (mma bf16): conv(32->64,4x4,pad1)+prelu+pool2. grid=BL/2, block=256.
// ---------------------------------------------------------------------------
#define C2_STR  20
#define C2_IMGW (121 * C2_STR)              // 2420 u32 per image per plane
#define C2_HALF (2 * C2_IMGW)               // 4840
#define SMEM_C2 (2 * C2_HALF * 4)           // 38720 B

__global__ void __launch_bounds__(256, 2)
k_conv2_mma(const float* __restrict__ b, const float* __restrict__ ap) {
    extern __shared__ uint32_t sm2[];
    uint32_t* sHi = sm2;
    uint32_t* sLo = sm2 + C2_HALF;
    const int tid = threadIdx.x;
    const int wid = tid >> 5;
    const int lid = tid & 31;
    const int bl  = blockIdx.x;             // image pair

    for (int i = tid; i < 2 * C2_HALF; i += 256) sm2[i] = 0u;
    __syncthreads();
    const float* src = g_s1 + bl * 2 * 2592;
    for (int i = tid; i < 2592; i += 256) {
        int img = i / 1296;
        int r   = i - img * 1296;
        int pr  = r / 81;
        int pix = r - pr * 81;
        int y   = pix / 9;
        int x   = pix - y * 9;
        float v0 = src[img * 2592 + (2 * pr) * 81 + pix];
        float v1 = src[img * 2592 + (2 * pr + 1) * 81 + pix];
        uint32_t hp, lp;
        split2(v0, v1, hp, lp);
        int idx = img * C2_IMGW + ((y + 1) * 11 + (x + 1)) * C2_STR + pr;
        sHi[idx] = hp;
        sLo[idx] = lp;
    }
    __syncthreads();

    const int img = wid >> 2;
    int base[2];
#pragma unroll
    for (int j = 0; j < 2; ++j) {
        int m   = wid * 16 + (lid >> 2) + j * 8;
        int pix = m & 63;
        int oy  = pix >> 3;
        int ox  = pix & 7;
        base[j] = img * C2_IMGW + (oy * 11 + ox) * C2_STR;
    }

    float4 acc[8];
#pragma unroll
    for (int nf = 0; nf < 8; ++nf) acc[nf] = make_float4(0.f, 0.f, 0.f, 0.f);

    const int cb = lid & 3;
    for (int p = 0; p < 16; ++p) {
        const int off = ((p >> 2) * 11 + (p & 3)) * C2_STR;
#pragma unroll
        for (int g = 0; g < 2; ++g) {
            const uint4* gB = g_w2B + ((p * 2 + g) * 32 + lid) * 8;
            const int c  = g * 8 + cb;
            const int i0 = base[0] + off + c;
            const int i1 = base[1] + off + c;
            uint32_t ha0 = sHi[i0], ha1 = sHi[i1];
            uint32_t ha2 = sHi[i0 + 4], ha3 = sHi[i1 + 4];
            uint32_t la0 = sLo[i0], la1 = sLo[i1];
            uint32_t la2 = sLo[i0 + 4], la3 = sLo[i1 + 4];
#pragma unroll
            for (int nf = 0; nf < 8; ++nf) {
                uint4 Bv = gB[nf];
                mma_bf16(acc[nf], ha0, ha1, ha2, ha3, Bv.x, Bv.y);
                mma_bf16(acc[nf], la0, la1, la2, la3, Bv.x, Bv.y);
                mma_bf16(acc[nf], ha0, ha1, ha2, ha3, Bv.z, Bv.w);
            }
        }
    }
    __syncthreads();   // reuse smem as fp32 stage: 128 rows x stride 65

    const float a = *ap;
    float* stage = (float*)sm2;
    {
        const int r0  = wid * 16 + (lid >> 2);
        const int oc0 = 2 * (lid & 3);
#pragma unroll
        for (int nf = 0; nf < 8; ++nf) {
            int ca = nf * 8 + oc0;
            float ba = b[ca], bb = b[ca + 1];
            stage[r0 * 65 + ca]           = prelu(acc[nf].x + ba, a);
            stage[r0 * 65 + ca + 1]       = prelu(acc[nf].y + bb, a);
            stage[(r0 + 8) * 65 + ca]     = prelu(acc[nf].z + ba, a);
            stage[(r0 + 8) * 65 + ca + 1] = prelu(acc[nf].w + bb, a);
        }
    }
    __syncthreads();

    for (int i = tid; i < 2048; i += 256) {
        int im  = i >> 10;
        int rem = i & 1023;
        int oc  = rem >> 4;
        int pp  = rem & 15;
        int py  = pp >> 2;
        int px  = pp & 3;
        int m00 = im * 64 + (2 * py) * 8 + 2 * px;
        float v = fmaxf(fmaxf(stage[m00 * 65 + oc],       stage[(m00 + 1) * 65 + oc]),
                        fmaxf(stage[(m00 + 8) * 65 + oc], stage[(m00 + 9) * 65 + oc]));
        g_s2[((bl * 2 + im) * 64 + oc) * 16 + py * 4 + px] = v;
    }
}

// ---------------------------------------------------------------------------
// Stage 3 (scalar): conv(64->64,3x3,pad0)+prelu+flatten
// ---------------------------------------------------------------------------
__global__ void k_conv3(const float* __restrict__ w,
                        const float* __restrict__ b,
                        const float* __restrict__ ap) {
    extern __shared__ float smem[];
    float* sW  = smem;             // 64*577 = 36928
    float* sIn = smem + 36928;     // 8*1024 = 8192
    const int tid = threadIdx.x;
    const int bl0 = blockIdx.x * 8;

    for (int k = tid; k < 64 * 576; k += 256) {
        int oc = k / 576;
        sW[oc * 577 + (k % 576)] = w[k];
    }
    const float* src = g_s2 + bl0 * 1024;
    for (int i = tid; i < 8192; i += 256) sIn[i] = src[i];
    __syncthreads();

    const int oc  = tid >> 2;
    const int pos = tid & 3;
    const int yy  = pos >> 1;
    const int xx  = pos & 1;
    const float bias = b[oc];
    const float a = *ap;

    float acc[8];
#pragma unroll
    for (int i = 0; i < 8; ++i) acc[i] = bias;

    for (int ic = 0; ic < 64; ++ic) {
        const float* wv = sW + oc * 577 + ic * 9;
        float wr[9];
#pragma unroll
        for (int j = 0; j < 9; ++j) wr[j] = wv[j];
#pragma unroll
        for (int img = 0; img < 8; ++img) {
            const float* ip = sIn + img * 1024 + ic * 16;
#pragma unroll
            for (int ky = 0; ky < 3; ++ky)
#pragma unroll
                for (int kx = 0; kx < 3; ++kx)
                    acc[img] = fmaf(ip[(yy + ky) * 4 + (xx + kx)], wr[ky * 3 + kx], acc[img]);
        }
    }
#pragma unroll
    for (int img = 0; img < 8; ++img) {
        g_s3[(bl0 + img) * 256 + oc * 4 + pos] = prelu(acc[img], a);
    }
}

// ---------------------------------------------------------------------------
// FC heads
// ---------------------------------------------------------------------------
__global__ void k_fc(const float* __restrict__ fc1_w, const float* __restrict__ fc1_b,
                     const float* __restrict__ a4,
                     const float* __restrict__ fc2_w, const float* __restrict__ fc2_b,
                     const float* __restrict__ a5,
                     const float* __restrict__ fc3_w, const float* __restrict__ fc3_b,
                     float* __restrict__ out) {
    __shared__ float feat[256];
    __shared__ float h1[128];
    __shared__ float h2[64];
    const int bl  = blockIdx.x;
    const int l   = bl % 6;
    const int tid = threadIdx.x;

    feat[tid]       = g_s3[bl * 256 + tid];
    feat[tid + 128] = g_s3[bl * 256 + 128 + tid];
    __syncthreads();

    {
        float acc = fc1_b[l * 128 + tid];
        const float* W = fc1_w + l * 256 * 128 + tid;
#pragma unroll 8
        for (int i = 0; i < 256; ++i) acc = fmaf(feat[i], W[i * 128], acc);
        float av = a4[l];
        h1[tid] = prelu(acc, av);
    }
    __syncthreads();
    if (tid < 64) {
        float acc = fc2_b[l * 64 + tid];
        const float* W = fc2_w + l * 128 * 64 + tid;
#pragma unroll 8
        for (int i = 0; i < 128; ++i) acc = fmaf(h1[i], W[i * 64], acc);
        float av = a5[l];
        h2[tid] = prelu(acc, av);
    }
    __syncthreads();
    if (tid < 4) {
        float acc = fc3_b[l * 4 + tid];
        const float* W = fc3_w + l * 64 * 4 + tid;
#pragma unroll
        for (int i = 0; i < 64; ++i) acc = fmaf(h2[i], W[i * 4], acc);
        out[bl * 4 + tid] = acc;
    }
}

// ---------------------------------------------------------------------------
extern "C" void kernel_launch(void* const* d_in, const int* in_sizes, int n_in,
                              void* d_out, int out_size) {
    const float* x     = (const float*)d_in[0];
    const float* w0    = (const float*)d_in[1];
    const float* b0    = (const float*)d_in[2];
    const float* w1    = (const float*)d_in[3];
    const float* b1    = (const float*)d_in[4];
    const float* w2    = (const float*)d_in[5];
    const float* b2    = (const float*)d_in[6];
    const float* w3    = (const float*)d_in[7];
    const float* b3    = (const float*)d_in[8];
    const float* a0    = (const float*)d_in[9];
    const float* a1    = (const float*)d_in[10];
    const float* a2    = (const float*)d_in[11];
    const float* a3    = (const float*)d_in[12];
    const float* fc1_w = (const float*)d_in[13];
    const float* fc1_b = (const float*)d_in[14];
    const float* a4    = (const float*)d_in[15];
    const float* fc2_w = (const float*)d_in[16];
    const float* fc2_b = (const float*)d_in[17];
    const float* a5    = (const float*)d_in[18];
    const float* fc3_w = (const float*)d_in[19];
    const float* fc3_b = (const float*)d_in[20];
    float* out = (float*)d_out;

    const int smem3 = (36928 + 8192) * 4;

    cudaFuncSetAttribute(k_conv0_mma, cudaFuncAttributeMaxDynamicSharedMemorySize, SMEM_C0);
    cudaFuncSetAttribute(k_conv1_mma, cudaFuncAttributeMaxDynamicSharedMemorySize, SMEM_C1);
    cudaFuncSetAttribute(k_conv2_mma, cudaFuncAttributeMaxDynamicSharedMemorySize, SMEM_C2);
    cudaFuncSetAttribute(k_conv3, cudaFuncAttributeMaxDynamicSharedMemorySize, smem3);

    k_w0prep<<<7, 128>>>(w0);
    k_w1prep<<<dim3(25, 2), 128>>>(w1);
    k_w2prep<<<dim3(16, 2), 256>>>(w2);
    k_conv0_mma<<<BL, 224, SMEM_C0>>>(x, b0, a0);
    k_conv1_mma<<<BL, 224, SMEM_C1>>>(b1, a1);
    k_conv2_mma<<<BL / 2, 256, SMEM_C2>>>(b2, a2);
    k_conv3<<<BL / 8, 256, smem3>>>(w3, b3, a3);
    k_fc<<<BL, 128>>>(fc1_w, fc1_b, a4, fc2_w, fc2_b, a5, fc3_w, fc3_b, out);
}

// round 9
// speedup vs baseline: 1.8921x; 1.1182x over previous
#include <cuda_runtime.h>
#include <cuda_bf16.h>
#include <cstdint>

// ---------------------------------------------------------------------------
// DQN_19198503813318 — R9: conv0 L1 fix (tile-pair B sharing + stride-54
// image layout). conv0/conv1/conv2 mma.sync bf16 x3; conv3/fc scalar.
// ---------------------------------------------------------------------------

#define BL 3072

__device__ float g_s0[BL * 32 * 21 * 21];   // after stage0 (planar)
__device__ float g_s1[BL * 32 * 9 * 9];     // after stage1
__device__ float g_s2[BL * 64 * 4 * 4];     // after stage2
__device__ float g_s3[BL * 256];            // flattened features
__device__ uint4 g_w0B[7 * 32 * 4];
__device__ uint4 g_w1B[25 * 2 * 32 * 4];
__device__ uint4 g_w2B[16 * 2 * 32 * 8];

__device__ __forceinline__ float prelu(float v, float a) {
    return v >= 0.0f ? v : a * v;
}

__device__ __forceinline__ uint32_t bf16pack(float vlo, float vhi) {
    uint32_t r;
    asm("cvt.rn.bf16x2.f32 %0, %1, %2;" : "=r"(r) : "f"(vhi), "f"(vlo));
    return r;
}

__device__ __forceinline__ void mma_bf16(float4& d,
                                         uint32_t a0, uint32_t a1, uint32_t a2, uint32_t a3,
                                         uint32_t b0, uint32_t b1) {
    asm volatile(
        "mma.sync.aligned.m16n8k16.row.col.f32.bf16.bf16.f32 "
        "{%0,%1,%2,%3}, {%4,%5,%6,%7}, {%8,%9}, {%0,%1,%2,%3};"
        : "+f"(d.x), "+f"(d.y), "+f"(d.z), "+f"(d.w)
        : "r"(a0), "r"(a1), "r"(a2), "r"(a3), "r"(b0), "r"(b1));
}

__device__ __forceinline__ void split2(float v0, float v1, uint32_t& hp, uint32_t& lp) {
    hp = bf16pack(v0, v1);
    float r0 = __uint_as_float(hp << 16);
    float r1 = __uint_as_float(hp & 0xffff0000u);
    lp = bf16pack(v0 - r0, v1 - r1);
}

// ---------------------------------------------------------------------------
// conv0 weight prep (same fragment layout as R8)
// ---------------------------------------------------------------------------
__global__ void k_w0prep(const float* __restrict__ w0) {
    const int c    = blockIdx.x;
    const int lane = threadIdx.x & 31;
    const int nf   = threadIdx.x >> 5;
    const int n    = nf * 8 + (lane >> 2);
    const int cb   = lane & 3;
    const int icp  = cb & 1;
    const int p0   = 4 * c + (cb >> 1);
    const int p2   = p0 + 2;
    float v0 = 0.f, v1 = 0.f, v2 = 0.f, v3 = 0.f;
    if (p0 < 25) {
        v0 = w0[n * 100 + (2 * icp) * 25 + p0];
        v1 = w0[n * 100 + (2 * icp + 1) * 25 + p0];
    }
    if (p2 < 25) {
        v2 = w0[n * 100 + (2 * icp) * 25 + p2];
        v3 = w0[n * 100 + (2 * icp + 1) * 25 + p2];
    }
    uint32_t hb0, lb0, hb1, lb1;
    split2(v0, v1, hb0, lb0);
    split2(v2, v3, hb1, lb1);
    g_w0B[(c * 32 + lane) * 4 + nf] = make_uint4(hb0, hb1, lb0, lb1);
}

__global__ void k_w1prep(const float* __restrict__ w1) {
    const int p    = blockIdx.x;
    const int g    = blockIdx.y;
    const int lane = threadIdx.x & 31;
    const int nf   = threadIdx.x >> 5;
    const int n    = nf * 8 + (lane >> 2);
    const int ic0  = g * 16 + 2 * (lane & 3);
    float v0 = w1[n * 800 + ic0 * 25 + p];
    float v1 = w1[n * 800 + (ic0 + 1) * 25 + p];
    float v8 = w1[n * 800 + (ic0 + 8) * 25 + p];
    float v9 = w1[n * 800 + (ic0 + 9) * 25 + p];
    uint32_t hb0, lb0, hb1, lb1;
    split2(v0, v1, hb0, lb0);
    split2(v8, v9, hb1, lb1);
    g_w1B[((p * 2 + g) * 32 + lane) * 4 + nf] = make_uint4(hb0, hb1, lb0, lb1);
}

__global__ void k_w2prep(const float* __restrict__ w2) {
    const int p    = blockIdx.x;
    const int g    = blockIdx.y;
    const int lane = threadIdx.x & 31;
    const int nf   = threadIdx.x >> 5;
    const int n    = nf * 8 + (lane >> 2);
    const int ic0  = g * 16 + 2 * (lane & 3);
    float v0 = w2[n * 512 + ic0 * 16 + p];
    float v1 = w2[n * 512 + (ic0 + 1) * 16 + p];
    float v8 = w2[n * 512 + (ic0 + 8) * 16 + p];
    float v9 = w2[n * 512 + (ic0 + 9) * 16 + p];
    uint32_t hb0, lb0, hb1, lb1;
    split2(v0, v1, hb0, lb0);
    split2(v8, v9, hb1, lb1);
    g_w2B[((p * 2 + g) * 32 + lane) * 8 + nf] = make_uint4(hb0, hb1, lb0, lb1);
}

// ---------------------------------------------------------------------------
// Stage 0 (mma bf16): conv(4->32,5x5,pad1)+prelu+pool2. grid=BL, block=224.
// M pooled-quad-major; pooling via shfl_xor(4),(8). Pixel stride 54
// (2*54 = 108 == 12 mod 32 -> distinct r-banks, max 2-way conflict).
// Tile pairs share B fragment loads (halves LDG wavefronts).
// ---------------------------------------------------------------------------
#define C0_PIX  54
#define C0_HALF (47 * C0_PIX * 2)       // 5076 u32 per plane
#define SMEM_C0 (2 * C0_HALF * 4)       // 40608 B

__global__ void __launch_bounds__(224, 3)
k_conv0_mma(const float* __restrict__ x,
            const float* __restrict__ b, const float* __restrict__ ap) {
    extern __shared__ uint32_t sm0[];
    uint32_t* sHi = sm0;
    uint32_t* sLo = sm0 + C0_HALF;
    const int tid = threadIdx.x;
    const int wid = tid >> 5;
    const int lid = tid & 31;
    const int bl  = blockIdx.x;

    for (int i = tid; i < 2 * C0_HALF; i += 224) sm0[i] = 0u;
    __syncthreads();
    const float* xb = x + bl * 8100;
    for (int i = tid; i < 4050; i += 224) {
        int pix = i >> 1;
        int pr  = i & 1;
        int y   = pix / 45;
        int xx  = pix - y * 45;
        float v0 = xb[(2 * pr) * 2025 + pix];
        float v1 = xb[(2 * pr + 1) * 2025 + pix];
        uint32_t hp, lp;
        split2(v0, v1, hp, lp);
        int idx = ((y + 1) * C0_PIX + (xx + 1)) * 2 + pr;
        sHi[idx] = hp;
        sLo[idx] = lp;
    }
    __syncthreads();

    const int cb  = lid & 3;
    const int icp = cb & 1;
    int off0[7], off2[7];
#pragma unroll
    for (int c = 0; c < 7; ++c) {
        int p0 = 4 * c + (cb >> 1);
        int p2 = p0 + 2;
        if (p0 > 24) p0 = 24;
        if (p2 > 24) p2 = 24;
        off0[c] = ((p0 / 5) * C0_PIX + (p0 % 5)) * 2 + icp;
        off2[c] = ((p2 / 5) * C0_PIX + (p2 % 5)) * 2 + icp;
    }
    float bx[4], by[4];
#pragma unroll
    for (int nf = 0; nf < 4; ++nf) {
        bx[nf] = b[nf * 8 + 2 * cb];
        by[nf] = b[nf * 8 + 2 * cb + 1];
    }
    const float a = *ap;
    float* out = g_s0 + bl * 14112;
    const bool wr = ((lid >> 2) & 3) == 0;
    const int qoff = (lid >= 16) ? 1 : 0;

    for (int tp = 0; tp < 8; ++tp) {
        int rb[2][2];
#pragma unroll
        for (int u = 0; u < 2; ++u) {
            const int tt = wid * 16 + tp * 2 + u;
#pragma unroll
            for (int j = 0; j < 2; ++j) {
                int m = tt * 16 + (lid >> 2) + j * 8;
                if (m >= 1764) m = 0;
                int q = m >> 2, s = m & 3;
                int yy = 2 * (q / 21) + (s >> 1);
                int xx = 2 * (q % 21) + (s & 1);
                rb[u][j] = (yy * C0_PIX + xx) * 2;
            }
        }
        float4 acc[2][4];
#pragma unroll
        for (int u = 0; u < 2; ++u)
#pragma unroll
            for (int nf = 0; nf < 4; ++nf) acc[u][nf] = make_float4(0.f, 0.f, 0.f, 0.f);

#pragma unroll
        for (int c = 0; c < 7; ++c) {
            const uint4* gB = g_w0B + (c * 32 + lid) * 4;
            uint4 B0 = gB[0], B1 = gB[1], B2 = gB[2], B3 = gB[3];
#pragma unroll
            for (int u = 0; u < 2; ++u) {
                uint32_t ha0 = sHi[rb[u][0] + off0[c]], ha1 = sHi[rb[u][1] + off0[c]];
                uint32_t ha2 = sHi[rb[u][0] + off2[c]], ha3 = sHi[rb[u][1] + off2[c]];
                uint32_t la0 = sLo[rb[u][0] + off0[c]], la1 = sLo[rb[u][1] + off0[c]];
                uint32_t la2 = sLo[rb[u][0] + off2[c]], la3 = sLo[rb[u][1] + off2[c]];
                mma_bf16(acc[u][0], ha0, ha1, ha2, ha3, B0.x, B0.y);
                mma_bf16(acc[u][1], ha0, ha1, ha2, ha3, B1.x, B1.y);
                mma_bf16(acc[u][2], ha0, ha1, ha2, ha3, B2.x, B2.y);
                mma_bf16(acc[u][3], ha0, ha1, ha2, ha3, B3.x, B3.y);
                mma_bf16(acc[u][0], la0, la1, la2, la3, B0.x, B0.y);
                mma_bf16(acc[u][1], la0, la1, la2, la3, B1.x, B1.y);
                mma_bf16(acc[u][2], la0, la1, la2, la3, B2.x, B2.y);
                mma_bf16(acc[u][3], la0, la1, la2, la3, B3.x, B3.y);
                mma_bf16(acc[u][0], ha0, ha1, ha2, ha3, B0.z, B0.w);
                mma_bf16(acc[u][1], ha0, ha1, ha2, ha3, B1.z, B1.w);
                mma_bf16(acc[u][2], ha0, ha1, ha2, ha3, B2.z, B2.w);
                mma_bf16(acc[u][3], ha0, ha1, ha2, ha3, B3.z, B3.w);
            }
        }
#pragma unroll
        for (int u = 0; u < 2; ++u) {
            const int tt = wid * 16 + tp * 2 + u;
            const int qA = tt * 4 + qoff;
            const int qB = qA + 2;
#pragma unroll
            for (int nf = 0; nf < 4; ++nf) {
                float vx = prelu(acc[u][nf].x + bx[nf], a);
                float vy = prelu(acc[u][nf].y + by[nf], a);
                float vz = prelu(acc[u][nf].z + bx[nf], a);
                float vw = prelu(acc[u][nf].w + by[nf], a);
                vx = fmaxf(vx, __shfl_xor_sync(0xffffffffu, vx, 4));
                vx = fmaxf(vx, __shfl_xor_sync(0xffffffffu, vx, 8));
                vy = fmaxf(vy, __shfl_xor_sync(0xffffffffu, vy, 4));
                vy = fmaxf(vy, __shfl_xor_sync(0xffffffffu, vy, 8));
                vz = fmaxf(vz, __shfl_xor_sync(0xffffffffu, vz, 4));
                vz = fmaxf(vz, __shfl_xor_sync(0xffffffffu, vz, 8));
                vw = fmaxf(vw, __shfl_xor_sync(0xffffffffu, vw, 4));
                vw = fmaxf(vw, __shfl_xor_sync(0xffffffffu, vw, 8));
                if (wr) {
                    int oc0 = nf * 8 + 2 * cb;
                    if (qA < 441) {
                        out[oc0 * 441 + qA]       = vx;
                        out[(oc0 + 1) * 441 + qA] = vy;
                    }
                    if (qB < 441) {
                        out[oc0 * 441 + qB]       = vz;
                        out[(oc0 + 1) * 441 + qB] = vw;
                    }
                }
            }
        }
    }
}

// ---------------------------------------------------------------------------
// Stage 1 (mma bf16): conv(32->32,5x5,pad1)+prelu+pool2. grid=BL, block=224.
// ---------------------------------------------------------------------------
#define C1_STR  20
#define C1_HALF (484 * C1_STR)
#define SMEM_C1 (2 * C1_HALF * 4)

__global__ void __launch_bounds__(224, 2)
k_conv1_mma(const float* __restrict__ b, const float* __restrict__ ap) {
    extern __shared__ uint32_t sm1[];
    uint32_t* sHi = sm1;
    uint32_t* sLo = sm1 + C1_HALF;
    const int tid = threadIdx.x;
    const int wid = tid >> 5;
    const int lid = tid & 31;
    const int bl  = blockIdx.x;

    for (int i = tid; i < 2 * C1_HALF; i += 224) sm1[i] = 0u;
    __syncthreads();
    const float* src = g_s0 + bl * 14112;
    for (int i = tid; i < 7056; i += 224) {
        int pr  = i / 441;
        int pix = i - pr * 441;
        int y   = pix / 21;
        int x   = pix - y * 21;
        float v0 = src[(2 * pr) * 441 + pix];
        float v1 = src[(2 * pr + 1) * 441 + pix];
        uint32_t hp, lp;
        split2(v0, v1, hp, lp);
        int idx = ((y + 1) * 22 + (x + 1)) * C1_STR + pr;
        sHi[idx] = hp;
        sLo[idx] = lp;
    }
    __syncthreads();

    int base[3][2];
#pragma unroll
    for (int t = 0; t < 3; ++t) {
#pragma unroll
        for (int j = 0; j < 2; ++j) {
            int m  = (wid * 3 + t) * 16 + (lid >> 2) + j * 8;
            int mm = m < 324 ? m : 0;
            int ym = mm / 18;
            int xm = mm - ym * 18;
            base[t][j] = (ym * 22 + xm) * C1_STR;
        }
    }

    float4 acc[3][4];
#pragma unroll
    for (int t = 0; t < 3; ++t)
#pragma unroll
        for (int nf = 0; nf < 4; ++nf)
            acc[t][nf] = make_float4(0.f, 0.f, 0.f, 0.f);

    const int cb = lid & 3;
    for (int p = 0; p < 25; ++p) {
        const int ky = p / 5;
        const int kx = p - ky * 5;
        const int off = (ky * 22 + kx) * C1_STR;
#pragma unroll
        for (int g = 0; g < 2; ++g) {
            const uint4* gB = g_w1B + ((p * 2 + g) * 32 + lid) * 4;
            uint4 B0 = gB[0], B1 = gB[1], B2 = gB[2], B3 = gB[3];
            const int c = g * 8 + cb;
#pragma unroll
            for (int t = 0; t < 3; ++t) {
                const int i0 = base[t][0] + off + c;
                const int i1 = base[t][1] + off + c;
                uint32_t ha0 = sHi[i0], ha1 = sHi[i1];
                uint32_t ha2 = sHi[i0 + 4], ha3 = sHi[i1 + 4];
                uint32_t la0 = sLo[i0], la1 = sLo[i1];
                uint32_t la2 = sLo[i0 + 4], la3 = sLo[i1 + 4];
                mma_bf16(acc[t][0], ha0, ha1, ha2, ha3, B0.x, B0.y);
                mma_bf16(acc[t][1], ha0, ha1, ha2, ha3, B1.x, B1.y);
                mma_bf16(acc[t][2], ha0, ha1, ha2, ha3, B2.x, B2.y);
                mma_bf16(acc[t][3], ha0, ha1, ha2, ha3, B3.x, B3.y);
                mma_bf16(acc[t][0], la0, la1, la2, la3, B0.x, B0.y);
                mma_bf16(acc[t][1], la0, la1, la2, la3, B1.x, B1.y);
                mma_bf16(acc[t][2], la0, la1, la2, la3, B2.x, B2.y);
                mma_bf16(acc[t][3], la0, la1, la2, la3, B3.x, B3.y);
                mma_bf16(acc[t][0], ha0, ha1, ha2, ha3, B0.z, B0.w);
                mma_bf16(acc[t][1], ha0, ha1, ha2, ha3, B1.z, B1.w);
                mma_bf16(acc[t][2], ha0, ha1, ha2, ha3, B2.z, B2.w);
                mma_bf16(acc[t][3], ha0, ha1, ha2, ha3, B3.z, B3.w);
            }
        }
    }
    __syncthreads();

    const float a = *ap;
    float* stage = (float*)sm1;
    {
        const int r0 = (wid * 3) * 16 + (lid >> 2);
        const int oc0 = 2 * (lid & 3);
#pragma unroll
        for (int t = 0; t < 3; ++t) {
            int ra = r0 + t * 16;
            int rb = ra + 8;
#pragma unroll
            for (int nf = 0; nf < 4; ++nf) {
                int ca = nf * 8 + oc0;
                float ba = b[ca], bb = b[ca + 1];
                stage[ra * 33 + ca]     = prelu(acc[t][nf].x + ba, a);
                stage[ra * 33 + ca + 1] = prelu(acc[t][nf].y + bb, a);
                stage[rb * 33 + ca]     = prelu(acc[t][nf].z + ba, a);
                stage[rb * 33 + ca + 1] = prelu(acc[t][nf].w + bb, a);
            }
        }
    }
    __syncthreads();

    float* out = g_s1 + bl * 2592;
    for (int i = tid; i < 2592; i += 224) {
        int oc = i / 81;
        int pp = i - oc * 81;
        int py = pp / 9;
        int px = pp - py * 9;
        int m00 = (2 * py) * 18 + 2 * px;
        float v = fmaxf(fmaxf(stage[m00 * 33 + oc],        stage[(m00 + 1) * 33 + oc]),
                        fmaxf(stage[(m00 + 18) * 33 + oc], stage[(m00 + 19) * 33 + oc]));
        out[i] = v;
    }
}

// ---------------------------------------------------------------------------
// Stage 2 (mma bf16): conv(32->64,4x4,pad1)+prelu+pool2. grid=BL/2, block=256.
// ---------------------------------------------------------------------------
#define C2_STR  20
#define C2_IMGW (121 * C2_STR)
#define C2_HALF (2 * C2_IMGW)
#define SMEM_C2 (2 * C2_HALF * 4)

__global__ void __launch_bounds__(256, 2)
k_conv2_mma(const float* __restrict__ b, const float* __restrict__ ap) {
    extern __shared__ uint32_t sm2[];
    uint32_t* sHi = sm2;
    uint32_t* sLo = sm2 + C2_HALF;
    const int tid = threadIdx.x;
    const int wid = tid >> 5;
    const int lid = tid & 31;
    const int bl  = blockIdx.x;

    for (int i = tid; i < 2 * C2_HALF; i += 256) sm2[i] = 0u;
    __syncthreads();
    const float* src = g_s1 + bl * 2 * 2592;
    for (int i = tid; i < 2592; i += 256) {
        int img = i / 1296;
        int r   = i - img * 1296;
        int pr  = r / 81;
        int pix = r - pr * 81;
        int y   = pix / 9;
        int x   = pix - y * 9;
        float v0 = src[img * 2592 + (2 * pr) * 81 + pix];
        float v1 = src[img * 2592 + (2 * pr + 1) * 81 + pix];
        uint32_t hp, lp;
        split2(v0, v1, hp, lp);
        int idx = img * C2_IMGW + ((y + 1) * 11 + (x + 1)) * C2_STR + pr;
        sHi[idx] = hp;
        sLo[idx] = lp;
    }
    __syncthreads();

    const int img = wid >> 2;
    int base[2];
#pragma unroll
    for (int j = 0; j < 2; ++j) {
        int m   = wid * 16 + (lid >> 2) + j * 8;
        int pix = m & 63;
        int oy  = pix >> 3;
        int ox  = pix & 7;
        base[j] = img * C2_IMGW + (oy * 11 + ox) * C2_STR;
    }

    float4 acc[8];
#pragma unroll
    for (int nf = 0; nf < 8; ++nf) acc[nf] = make_float4(0.f, 0.f, 0.f, 0.f);

    const int cb = lid & 3;
    for (int p = 0; p < 16; ++p) {
        const int off = ((p >> 2) * 11 + (p & 3)) * C2_STR;
#pragma unroll
        for (int g = 0; g < 2; ++g) {
            const uint4* gB = g_w2B + ((p * 2 + g) * 32 + lid) * 8;
            const int c  = g * 8 + cb;
            const int i0 = base[0] + off + c;
            const int i1 = base[1] + off + c;
            uint32_t ha0 = sHi[i0], ha1 = sHi[i1];
            uint32_t ha2 = sHi[i0 + 4], ha3 = sHi[i1 + 4];
            uint32_t la0 = sLo[i0], la1 = sLo[i1];
            uint32_t la2 = sLo[i0 + 4], la3 = sLo[i1 + 4];
#pragma unroll
            for (int nf = 0; nf < 8; ++nf) {
                uint4 Bv = gB[nf];
                mma_bf16(acc[nf], ha0, ha1, ha2, ha3, Bv.x, Bv.y);
                mma_bf16(acc[nf], la0, la1, la2, la3, Bv.x, Bv.y);
                mma_bf16(acc[nf], ha0, ha1, ha2, ha3, Bv.z, Bv.w);
            }
        }
    }
    __syncthreads();

    const float a = *ap;
    float* stage = (float*)sm2;
    {
        const int r0  = wid * 16 + (lid >> 2);
        const int oc0 = 2 * (lid & 3);
#pragma unroll
        for (int nf = 0; nf < 8; ++nf) {
            int ca = nf * 8 + oc0;
            float ba = b[ca], bb = b[ca + 1];
            stage[r0 * 65 + ca]           = prelu(acc[nf].x + ba, a);
            stage[r0 * 65 + ca + 1]       = prelu(acc[nf].y + bb, a);
            stage[(r0 + 8) * 65 + ca]     = prelu(acc[nf].z + ba, a);
            stage[(r0 + 8) * 65 + ca + 1] = prelu(acc[nf].w + bb, a);
        }
    }
    __syncthreads();

    for (int i = tid; i < 2048; i += 256) {
        int im  = i >> 10;
        int rem = i & 1023;
        int oc  = rem >> 4;
        int pp  = rem & 15;
        int py  = pp >> 2;
        int px  = pp & 3;
        int m00 = im * 64 + (2 * py) * 8 + 2 * px;
        float v = fmaxf(fmaxf(stage[m00 * 65 + oc],       stage[(m00 + 1) * 65 + oc]),
                        fmaxf(stage[(m00 + 8) * 65 + oc], stage[(m00 + 9) * 65 + oc]));
        g_s2[((bl * 2 + im) * 64 + oc) * 16 + py * 4 + px] = v;
    }
}

// ---------------------------------------------------------------------------
// Stage 3 (scalar): conv(64->64,3x3,pad0)+prelu+flatten
// ---------------------------------------------------------------------------
__global__ void k_conv3(const float* __restrict__ w,
                        const float* __restrict__ b,
                        const float* __restrict__ ap) {
    extern __shared__ float smem[];
    float* sW  = smem;             // 64*577 = 36928
    float* sIn = smem + 36928;     // 8*1024 = 8192
    const int tid = threadIdx.x;
    const int bl0 = blockIdx.x * 8;

    for (int k = tid; k < 64 * 576; k += 256) {
        int oc = k / 576;
        sW[oc * 577 + (k % 576)] = w[k];
    }
    const float* src = g_s2 + bl0 * 1024;
    for (int i = tid; i < 8192; i += 256) sIn[i] = src[i];
    __syncthreads();

    const int oc  = tid >> 2;
    const int pos = tid & 3;
    const int yy  = pos >> 1;
    const int xx  = pos & 1;
    const float bias = b[oc];
    const float a = *ap;

    float acc[8];
#pragma unroll
    for (int i = 0; i < 8; ++i) acc[i] = bias;

    for (int ic = 0; ic < 64; ++ic) {
        const float* wv = sW + oc * 577 + ic * 9;
        float wr[9];
#pragma unroll
        for (int j = 0; j < 9; ++j) wr[j] = wv[j];
#pragma unroll
        for (int img = 0; img < 8; ++img) {
            const float* ip = sIn + img * 1024 + ic * 16;
#pragma unroll
            for (int ky = 0; ky < 3; ++ky)
#pragma unroll
                for (int kx = 0; kx < 3; ++kx)
                    acc[img] = fmaf(ip[(yy + ky) * 4 + (xx + kx)], wr[ky * 3 + kx], acc[img]);
        }
    }
#pragma unroll
    for (int img = 0; img < 8; ++img) {
        g_s3[(bl0 + img) * 256 + oc * 4 + pos] = prelu(acc[img], a);
    }
}

// ---------------------------------------------------------------------------
// FC heads
// ---------------------------------------------------------------------------
__global__ void k_fc(const float* __restrict__ fc1_w, const float* __restrict__ fc1_b,
                     const float* __restrict__ a4,
                     const float* __restrict__ fc2_w, const float* __restrict__ fc2_b,
                     const float* __restrict__ a5,
                     const float* __restrict__ fc3_w, const float* __restrict__ fc3_b,
                     float* __restrict__ out) {
    __shared__ float feat[256];
    __shared__ float h1[128];
    __shared__ float h2[64];
    const int bl  = blockIdx.x;
    const int l   = bl % 6;
    const int tid = threadIdx.x;

    feat[tid]       = g_s3[bl * 256 + tid];
    feat[tid + 128] = g_s3[bl * 256 + 128 + tid];
    __syncthreads();

    {
        float acc = fc1_b[l * 128 + tid];
        const float* W = fc1_w + l * 256 * 128 + tid;
#pragma unroll 8
        for (int i = 0; i < 256; ++i) acc = fmaf(feat[i], W[i * 128], acc);
        float av = a4[l];
        h1[tid] = prelu(acc, av);
    }
    __syncthreads();
    if (tid < 64) {
        float acc = fc2_b[l * 64 + tid];
        const float* W = fc2_w + l * 128 * 64 + tid;
#pragma unroll 8
        for (int i = 0; i < 128; ++i) acc = fmaf(h1[i], W[i * 64], acc);
        float av = a5[l];
        h2[tid] = prelu(acc, av);
    }
    __syncthreads();
    if (tid < 4) {
        float acc = fc3_b[l * 4 + tid];
        const float* W = fc3_w + l * 64 * 4 + tid;
#pragma unroll
        for (int i = 0; i < 64; ++i) acc = fmaf(h2[i], W[i * 4], acc);
        out[bl * 4 + tid] = acc;
    }
}

// ---------------------------------------------------------------------------
extern "C" void kernel_launch(void* const* d_in, const int* in_sizes, int n_in,
                              void* d_out, int out_size) {
    const float* x     = (const float*)d_in[0];
    const float* w0    = (const float*)d_in[1];
    const float* b0    = (const float*)d_in[2];
    const float* w1    = (const float*)d_in[3];
    const float* b1    = (const float*)d_in[4];
    const float* w2    = (const float*)d_in[5];
    const float* b2    = (const float*)d_in[6];
    const float* w3    = (const float*)d_in[7];
    const float* b3    = (const float*)d_in[8];
    const float* a0    = (const float*)d_in[9];
    const float* a1    = (const float*)d_in[10];
    const float* a2    = (const float*)d_in[11];
    const float* a3    = (const float*)d_in[12];
    const float* fc1_w = (const float*)d_in[13];
    const float* fc1_b = (const float*)d_in[14];
    const float* a4    = (const float*)d_in[15];
    const float* fc2_w = (const float*)d_in[16];
    const float* fc2_b = (const float*)d_in[17];
    const float* a5    = (const float*)d_in[18];
    const float* fc3_w = (const float*)d_in[19];
    const float* fc3_b = (const float*)d_in[20];
    float* out = (float*)d_out;

    const int smem3 = (36928 + 8192) * 4;

    cudaFuncSetAttribute(k_conv0_mma, cudaFuncAttributeMaxDynamicSharedMemorySize, SMEM_C0);
    cudaFuncSetAttribute(k_conv1_mma, cudaFuncAttributeMaxDynamicSharedMemorySize, SMEM_C1);
    cudaFuncSetAttribute(k_conv2_mma, cudaFuncAttributeMaxDynamicSharedMemorySize, SMEM_C2);
    cudaFuncSetAttribute(k_conv3, cudaFuncAttributeMaxDynamicSharedMemorySize, smem3);

    k_w0prep<<<7, 128>>>(w0);
    k_w1prep<<<dim3(25, 2), 128>>>(w1);
    k_w2prep<<<dim3(16, 2), 256>>>(w2);
    k_conv0_mma<<<BL, 224, SMEM_C0>>>(x, b0, a0);
    k_conv1_mma<<<BL, 224, SMEM_C1>>>(b1, a1);
    k_conv2_mma<<<BL / 2, 256, SMEM_C2>>>(b2, a2);
    k_conv3<<<BL / 8, 256, smem3>>>(w3, b3, a3);
    k_fc<<<BL, 128>>>(fc1_w, fc1_b, a4, fc2_w, fc2_b, a5, fc3_w, fc3_b, out);
}